// round 14
// baseline (speedup 1.0000x reference)
#include <cuda_runtime.h>
#include <cuda_fp16.h>
#include <math.h>

#define N_NODES 100000
#define N_EDGES 3200000
#define N_GRAPHS 64
#define NBLK 391                    // ceil(N_NODES/256)

// ---------------- scratch (device globals; no runtime allocation) ------------
__device__ __align__(16) int     g_cnt_in [N_NODES];
__device__ __align__(16) int     g_cnt_out[N_NODES];
__device__ __align__(16) int     g_rank   [N_EDGES];
__device__ __align__(16) int     g_rowptr [N_NODES + 1];
__device__              int      g_ctr;
__device__ __align__(16) int     g_srcsrt [N_EDGES];
__device__ __align__(16) float   g_ns [N_NODES];
__device__ __align__(16) float   g_nd [N_NODES];
__device__ __align__(16) __half  g_th[((size_t)N_NODES + 1) * 64]; // messages (+dummy)
__device__ __align__(16) __half  g_mh[((size_t)N_NODES + 1) * 64]; // activations (+dummy)
__device__ __align__(16) __half  g_hh[((size_t)N_NODES + 1) * 64]; // L3 messages (+dummy)
__device__ __align__(16) float   g_hg[N_GRAPHS * 64];
// packed hi/lo weights in padded smem layout: (K2 half2-rows) x (DOUT+1)
__device__ __align__(16) __half2 g_w1hi[64 * 65];
__device__ __align__(16) __half2 g_w1lo[64 * 65];
__device__ __align__(16) __half2 g_w2hi[32 * 129];
__device__ __align__(16) __half2 g_w2lo[32 * 129];
__device__ __align__(16) __half2 g_w3hi[64 * 65];
__device__ __align__(16) __half2 g_w3lo[64 * 65];

// ---------------- pack W helper --------------------------------------------------
__device__ __forceinline__ void wpack_one(const float* __restrict__ W,
                                          __half2* hi, __half2* lo,
                                          int i, int DOUT) {
    int k = i / DOUT, n = i % DOUT;
    float w = __ldg(&W[i]);
    __half h = __float2half_rn(w);
    __half l = __float2half_rn(w - __half2float(h));
    int WROW = DOUT + 1;
    ((__half*)hi)[((k >> 1) * WROW + n) * 2 + (k & 1)] = h;
    ((__half*)lo)[((k >> 1) * WROW + n) * 2 + (k & 1)] = l;
}

// ---------------- zero + weight packing (fused: one launch) ----------------------
__global__ void k_zero(const float* __restrict__ W1, const float* __restrict__ W2,
                       const float* __restrict__ W3) {
    int i = blockIdx.x * blockDim.x + threadIdx.x;
    if (i < N_NODES) { g_cnt_in[i] = 0; g_cnt_out[i] = 0; }
    if (i < N_GRAPHS * 64) g_hg[i] = 0.f;
    if (i == 0) g_ctr = 0;
    if (i < 32) {                                  // dummy zero rows for gather tails
        ((int*)(g_th + (size_t)N_NODES * 64))[i] = 0;
        ((int*)(g_mh + (size_t)N_NODES * 64))[i] = 0;
        ((int*)(g_hh + (size_t)N_NODES * 64))[i] = 0;
    }
    // weight packing (indices 0 .. 24575)
    if (i < 8192)            wpack_one(W1, g_w1hi, g_w1lo, i, 64);
    else if (i < 16384)      wpack_one(W2, g_w2hi, g_w2lo, i - 8192, 128);
    else if (i < 24576)      wpack_one(W3, g_w3hi, g_w3lo, i - 16384, 64);
}

// ---------------- degree histograms + free edge ranks (4 edges/thread) ----------
__global__ void k_hist(const int* __restrict__ src, const int* __restrict__ dst) {
    int i = blockIdx.x * blockDim.x + threadIdx.x;     // over N_EDGES/4
    if (i * 4 >= N_EDGES) return;
    int4 s4 = __ldg((const int4*)src + i);
    int4 d4 = __ldg((const int4*)dst + i);
    int4 r4;
    r4.x = atomicAdd(&g_cnt_in[d4.x], 1);
    r4.y = atomicAdd(&g_cnt_in[d4.y], 1);
    r4.z = atomicAdd(&g_cnt_in[d4.z], 1);
    r4.w = atomicAdd(&g_cnt_in[d4.w], 1);
    ((int4*)g_rank)[i] = r4;
    atomicAdd(&g_cnt_out[s4.x], 1);
    atomicAdd(&g_cnt_out[s4.y], 1);
    atomicAdd(&g_cnt_out[s4.z], 1);
    atomicAdd(&g_cnt_out[s4.w], 1);
}

// ---------------- single-pass "scan": disjoint (unordered) buckets + norms -------
__global__ void k_scanA() {
    __shared__ int sh[256];
    __shared__ int sbase;
    int i = blockIdx.x * 256 + threadIdx.x;
    int v = (i < N_NODES) ? g_cnt_in[i] : 0;
    sh[threadIdx.x] = v;
    __syncthreads();
#pragma unroll
    for (int off = 1; off < 256; off <<= 1) {
        int t = (threadIdx.x >= off) ? sh[threadIdx.x - off] : 0;
        __syncthreads();
        sh[threadIdx.x] += t;
        __syncthreads();
    }
    if (threadIdx.x == 255) sbase = atomicAdd(&g_ctr, sh[255]);
    __syncthreads();
    if (i < N_NODES) {
        g_rowptr[i] = sbase + sh[threadIdx.x] - v;       // exclusive within block
        g_ns[i] = rsqrtf(fmaxf((float)g_cnt_out[i], 1.f));
        g_nd[i] = rsqrtf(fmaxf((float)g_cnt_in [i], 1.f));
    }
}

// ---------------- bucket fill: atomic-free (4 edges/thread) ---------------------
__global__ void k_fill(const int* __restrict__ src, const int* __restrict__ dst) {
    int i = blockIdx.x * blockDim.x + threadIdx.x;
    if (i * 4 >= N_EDGES) return;
    int4 s4 = __ldg((const int4*)src + i);
    int4 d4 = __ldg((const int4*)dst + i);
    int4 r4 = ((const int4*)g_rank)[i];
    g_srcsrt[__ldg(&g_rowptr[d4.x]) + r4.x] = s4.x;
    g_srcsrt[__ldg(&g_rowptr[d4.y]) + r4.y] = s4.y;
    g_srcsrt[__ldg(&g_rowptr[d4.z]) + r4.z] = s4.z;
    g_srcsrt[__ldg(&g_rowptr[d4.w]) + r4.w] = s4.w;
}

// ---------------- tensor-core matmul (packed pre-split W) — layer 1 only ---------
template <int DIN, int DOUT, bool RELU, bool HASBIAS, bool SCALE, bool IN32>
__global__ void k_mmtc(const void* __restrict__ Xv,
                       const __half2* __restrict__ Whi, const __half2* __restrict__ Wlo,
                       const float* __restrict__ bias, const float* __restrict__ scale,
                       const float* __restrict__ inscale, __half* __restrict__ out) {
    constexpr int XROW = DIN + 8;
    constexpr int WROW = DOUT + 1;
    constexpr int K2   = DIN / 2;
    constexpr int NT   = DOUT / 8;
    constexpr int WU4  = K2 * WROW / 4;      // uint4 per packed matrix
    extern __shared__ char smem[];
    __half*  sX   = (__half*)smem;
    __half2* sWhi = (__half2*)(smem + 128 * XROW * 2);
    __half2* sWlo = sWhi + K2 * WROW;

    const int tid = threadIdx.x;
    const int wid = tid >> 5, lane = tid & 31;
    const int g = lane >> 2, tig = lane & 3;

    {
        const uint4* whi4 = (const uint4*)Whi;
        const uint4* wlo4 = (const uint4*)Wlo;
        uint4* shi4 = (uint4*)sWhi;
        uint4* slo4 = (uint4*)sWlo;
        for (int i = tid; i < WU4; i += 256) {
            shi4[i] = __ldg(&whi4[i]);
            slo4[i] = __ldg(&wlo4[i]);
        }
    }

    const int base = blockIdx.x * 128;
    constexpr int QPR = DIN / 8;
    for (int i = tid; i < 128 * QPR; i += 256) {
        int r = i / QPR, q = i % QPR;
        int n = base + r;
        uint4 v = make_uint4(0u, 0u, 0u, 0u);
        if (n < N_NODES) {
            if (IN32) {
                const float* X = (const float*)Xv;
                float s = __ldg(&inscale[n]);
                const float4* p = (const float4*)(X + (size_t)n * DIN) + q * 2;
                float4 u0 = __ldg(p), u1 = __ldg(p + 1);
                __half2 h0 = __float22half2_rn(make_float2(u0.x * s, u0.y * s));
                __half2 h1 = __float22half2_rn(make_float2(u0.z * s, u0.w * s));
                __half2 h2 = __float22half2_rn(make_float2(u1.x * s, u1.y * s));
                __half2 h3 = __float22half2_rn(make_float2(u1.z * s, u1.w * s));
                v.x = *(unsigned*)&h0; v.y = *(unsigned*)&h1;
                v.z = *(unsigned*)&h2; v.w = *(unsigned*)&h3;
            } else {
                const __half* X = (const __half*)Xv;
                v = __ldg((const uint4*)(X + (size_t)n * DIN) + q);
            }
        }
        *(uint4*)(sX + r * XROW + q * 8) = v;
    }
    __syncthreads();

    float c[NT][4];
#pragma unroll
    for (int t = 0; t < NT; t++) { c[t][0] = c[t][1] = c[t][2] = c[t][3] = 0.f; }

    const __half* xw = sX + wid * 16 * XROW;
#pragma unroll
    for (int k0 = 0; k0 < DIN; k0 += 16) {
        const __half* ap = xw + (size_t)(lane & 15) * XROW + k0 + ((lane >> 4) << 3);
        unsigned aaddr = (unsigned)__cvta_generic_to_shared(ap);
        unsigned a0, a1, a2, a3;
        asm volatile("ldmatrix.sync.aligned.m8n8.x4.shared.b16 {%0,%1,%2,%3}, [%4];"
                     : "=r"(a0), "=r"(a1), "=r"(a2), "=r"(a3) : "r"(aaddr));
#pragma unroll
        for (int t = 0; t < NT; t++) {
            unsigned bh0 = *(const unsigned*)&sWhi[(k0 / 2 + tig)     * WROW + t * 8 + g];
            unsigned bh1 = *(const unsigned*)&sWhi[(k0 / 2 + 4 + tig) * WROW + t * 8 + g];
            asm volatile("mma.sync.aligned.m16n8k16.row.col.f32.f16.f16.f32 "
                         "{%0,%1,%2,%3}, {%4,%5,%6,%7}, {%8,%9}, {%0,%1,%2,%3};"
                         : "+f"(c[t][0]), "+f"(c[t][1]), "+f"(c[t][2]), "+f"(c[t][3])
                         : "r"(a0), "r"(a1), "r"(a2), "r"(a3), "r"(bh0), "r"(bh1));
            unsigned bl0 = *(const unsigned*)&sWlo[(k0 / 2 + tig)     * WROW + t * 8 + g];
            unsigned bl1 = *(const unsigned*)&sWlo[(k0 / 2 + 4 + tig) * WROW + t * 8 + g];
            asm volatile("mma.sync.aligned.m16n8k16.row.col.f32.f16.f16.f32 "
                         "{%0,%1,%2,%3}, {%4,%5,%6,%7}, {%8,%9}, {%0,%1,%2,%3};"
                         : "+f"(c[t][0]), "+f"(c[t][1]), "+f"(c[t][2]), "+f"(c[t][3])
                         : "r"(a0), "r"(a1), "r"(a2), "r"(a3), "r"(bl0), "r"(bl1));
        }
    }

    int n0 = base + wid * 16 + g;
    int n1 = n0 + 8;
    float s0 = 1.f, s1 = 1.f;
    if (SCALE) {
        if (n0 < N_NODES) s0 = __ldg(&scale[n0]);
        if (n1 < N_NODES) s1 = __ldg(&scale[n1]);
    }
#pragma unroll
    for (int t = 0; t < NT; t++) {
        int j0 = t * 8 + tig * 2;
        float bb0 = 0.f, bb1 = 0.f;
        if (HASBIAS) { bb0 = __ldg(&bias[j0]); bb1 = __ldg(&bias[j0 + 1]); }
        if (n0 < N_NODES) {
            float r0 = c[t][0] + bb0, r1 = c[t][1] + bb1;
            if (RELU) { r0 = fmaxf(r0, 0.f); r1 = fmaxf(r1, 0.f); }
            r0 *= s0; r1 *= s0;
            __half2 h = __float22half2_rn(make_float2(r0, r1));
            *(unsigned*)(out + (size_t)n0 * DOUT + j0) = *(unsigned*)&h;
        }
        if (n1 < N_NODES) {
            float r0 = c[t][2] + bb0, r1 = c[t][3] + bb1;
            if (RELU) { r0 = fmaxf(r0, 0.f); r1 = fmaxf(r1, 0.f); }
            r0 *= s1; r1 *= s1;
            __half2 h = __float22half2_rn(make_float2(r0, r1));
            *(unsigned*)(out + (size_t)n1 * DOUT + j0) = *(unsigned*)&h;
        }
    }
}

// ---------------- fused mm2+mm3: out = (relu(X@W2 + b2) * ns) @ W3 ---------------
__global__ void k_mm23(const __half* __restrict__ X,
                       const __half2* __restrict__ W2hi, const __half2* __restrict__ W2lo,
                       const float* __restrict__ b2, const float* __restrict__ ns,
                       const __half2* __restrict__ W3hi, const __half2* __restrict__ W3lo,
                       __half* __restrict__ out) {
    extern __shared__ char smem[];
    __half*  sX    = (__half*)smem;
    __half2* sW2hi = (__half2*)(smem + 18432);
    __half2* sW2lo = (__half2*)(smem + 34944);
    __half*  sH    = (__half*)(smem + 51456);
    __half2* sW3hi = (__half2*)(smem + 86272);
    __half2* sW3lo = (__half2*)(smem + 102912);

    const int tid = threadIdx.x;
    const int wid = tid >> 5, lane = tid & 31;
    const int g = lane >> 2, tig = lane & 3;
    const int base = blockIdx.x * 128;

    // W2: 1032 uint4; W3: 1040 uint4
    {
        const uint4* a = (const uint4*)W2hi; const uint4* b = (const uint4*)W2lo;
        uint4* sa = (uint4*)sW2hi; uint4* sb = (uint4*)sW2lo;
        for (int i = tid; i < 1032; i += 256) {
            sa[i] = __ldg(&a[i]); sb[i] = __ldg(&b[i]);
        }
        const uint4* c4 = (const uint4*)W3hi; const uint4* d4 = (const uint4*)W3lo;
        uint4* sc = (uint4*)sW3hi; uint4* sd = (uint4*)sW3lo;
        for (int i = tid; i < 1040; i += 256) {
            sc[i] = __ldg(&c4[i]); sd[i] = __ldg(&d4[i]);
        }
    }

    for (int i = tid; i < 128 * 8; i += 256) {
        int r = i / 8, q = i % 8;
        int n = base + r;
        uint4 v = make_uint4(0u, 0u, 0u, 0u);
        if (n < N_NODES) v = __ldg((const uint4*)(X + (size_t)n * 64) + q);
        *(uint4*)(sX + r * 72 + q * 8) = v;
    }
    __syncthreads();

    float c[16][4];
#pragma unroll
    for (int t = 0; t < 16; t++) { c[t][0] = c[t][1] = c[t][2] = c[t][3] = 0.f; }

    {
        const __half* xw = sX + wid * 16 * 72;
#pragma unroll
        for (int k0 = 0; k0 < 64; k0 += 16) {
            const __half* ap = xw + (size_t)(lane & 15) * 72 + k0 + ((lane >> 4) << 3);
            unsigned aaddr = (unsigned)__cvta_generic_to_shared(ap);
            unsigned a0, a1, a2, a3;
            asm volatile("ldmatrix.sync.aligned.m8n8.x4.shared.b16 {%0,%1,%2,%3}, [%4];"
                         : "=r"(a0), "=r"(a1), "=r"(a2), "=r"(a3) : "r"(aaddr));
#pragma unroll
            for (int t = 0; t < 16; t++) {
                unsigned bh0 = *(const unsigned*)&sW2hi[(k0 / 2 + tig)     * 129 + t * 8 + g];
                unsigned bh1 = *(const unsigned*)&sW2hi[(k0 / 2 + 4 + tig) * 129 + t * 8 + g];
                asm volatile("mma.sync.aligned.m16n8k16.row.col.f32.f16.f16.f32 "
                             "{%0,%1,%2,%3}, {%4,%5,%6,%7}, {%8,%9}, {%0,%1,%2,%3};"
                             : "+f"(c[t][0]), "+f"(c[t][1]), "+f"(c[t][2]), "+f"(c[t][3])
                             : "r"(a0), "r"(a1), "r"(a2), "r"(a3), "r"(bh0), "r"(bh1));
                unsigned bl0 = *(const unsigned*)&sW2lo[(k0 / 2 + tig)     * 129 + t * 8 + g];
                unsigned bl1 = *(const unsigned*)&sW2lo[(k0 / 2 + 4 + tig) * 129 + t * 8 + g];
                asm volatile("mma.sync.aligned.m16n8k16.row.col.f32.f16.f16.f32 "
                             "{%0,%1,%2,%3}, {%4,%5,%6,%7}, {%8,%9}, {%0,%1,%2,%3};"
                             : "+f"(c[t][0]), "+f"(c[t][1]), "+f"(c[t][2]), "+f"(c[t][3])
                             : "r"(a0), "r"(a1), "r"(a2), "r"(a3), "r"(bl0), "r"(bl1));
            }
        }
    }

    {
        int ln0 = wid * 16 + g;
        int ln1 = ln0 + 8;
        int n0 = base + ln0, n1 = base + ln1;
        float s0 = (n0 < N_NODES) ? __ldg(&ns[n0]) : 0.f;
        float s1 = (n1 < N_NODES) ? __ldg(&ns[n1]) : 0.f;
#pragma unroll
        for (int t = 0; t < 16; t++) {
            int j0 = t * 8 + tig * 2;
            float bb0 = __ldg(&b2[j0]), bb1 = __ldg(&b2[j0 + 1]);
            float r0 = fmaxf(c[t][0] + bb0, 0.f) * s0;
            float r1 = fmaxf(c[t][1] + bb1, 0.f) * s0;
            float r2 = fmaxf(c[t][2] + bb0, 0.f) * s1;
            float r3 = fmaxf(c[t][3] + bb1, 0.f) * s1;
            __half2 h0 = __float22half2_rn(make_float2(r0, r1));
            __half2 h1 = __float22half2_rn(make_float2(r2, r3));
            *(unsigned*)(sH + ln0 * 136 + j0) = *(unsigned*)&h0;
            *(unsigned*)(sH + ln1 * 136 + j0) = *(unsigned*)&h1;
        }
    }
    __syncthreads();

    float c2[8][4];
#pragma unroll
    for (int t = 0; t < 8; t++) { c2[t][0] = c2[t][1] = c2[t][2] = c2[t][3] = 0.f; }

    {
        const __half* xw = sH + wid * 16 * 136;
#pragma unroll
        for (int k0 = 0; k0 < 128; k0 += 16) {
            const __half* ap = xw + (size_t)(lane & 15) * 136 + k0 + ((lane >> 4) << 3);
            unsigned aaddr = (unsigned)__cvta_generic_to_shared(ap);
            unsigned a0, a1, a2, a3;
            asm volatile("ldmatrix.sync.aligned.m8n8.x4.shared.b16 {%0,%1,%2,%3}, [%4];"
                         : "=r"(a0), "=r"(a1), "=r"(a2), "=r"(a3) : "r"(aaddr));
#pragma unroll
            for (int t = 0; t < 8; t++) {
                unsigned bh0 = *(const unsigned*)&sW3hi[(k0 / 2 + tig)     * 65 + t * 8 + g];
                unsigned bh1 = *(const unsigned*)&sW3hi[(k0 / 2 + 4 + tig) * 65 + t * 8 + g];
                asm volatile("mma.sync.aligned.m16n8k16.row.col.f32.f16.f16.f32 "
                             "{%0,%1,%2,%3}, {%4,%5,%6,%7}, {%8,%9}, {%0,%1,%2,%3};"
                             : "+f"(c2[t][0]), "+f"(c2[t][1]), "+f"(c2[t][2]), "+f"(c2[t][3])
                             : "r"(a0), "r"(a1), "r"(a2), "r"(a3), "r"(bh0), "r"(bh1));
                unsigned bl0 = *(const unsigned*)&sW3lo[(k0 / 2 + tig)     * 65 + t * 8 + g];
                unsigned bl1 = *(const unsigned*)&sW3lo[(k0 / 2 + 4 + tig) * 65 + t * 8 + g];
                asm volatile("mma.sync.aligned.m16n8k16.row.col.f32.f16.f16.f32 "
                             "{%0,%1,%2,%3}, {%4,%5,%6,%7}, {%8,%9}, {%0,%1,%2,%3};"
                             : "+f"(c2[t][0]), "+f"(c2[t][1]), "+f"(c2[t][2]), "+f"(c2[t][3])
                             : "r"(a0), "r"(a1), "r"(a2), "r"(a3), "r"(bl0), "r"(bl1));
            }
        }
    }

    {
        int n0 = base + wid * 16 + g;
        int n1 = n0 + 8;
#pragma unroll
        for (int t = 0; t < 8; t++) {
            int j0 = t * 8 + tig * 2;
            if (n0 < N_NODES) {
                __half2 h = __float22half2_rn(make_float2(c2[t][0], c2[t][1]));
                *(unsigned*)(out + (size_t)n0 * 64 + j0) = *(unsigned*)&h;
            }
            if (n1 < N_NODES) {
                __half2 h = __float22half2_rn(make_float2(c2[t][2], c2[t][3]));
                *(unsigned*)(out + (size_t)n1 * 64 + j0) = *(unsigned*)&h;
            }
        }
    }
}

// ---------------- CSR gather: warp/node, HADD2-paired accumulate ------------------
// MODE 0: out(fp16) = sum * nd                  (L2 mm input, nd folded)
// MODE 1: out(fp16) = relu(sum*nd + b) * ns     (L1 output)
// MODE 2: out(fp16) = relu(sum*nd + b)          (L3 output, pool input)
template <int MODE>
__global__ void k_gather(const __half* __restrict__ tin, const float* __restrict__ bias,
                         __half* __restrict__ outp) {
    const int lane = threadIdx.x & 31;
    const int wid  = threadIdx.x >> 5;
    const int n    = blockIdx.x * 8 + wid;
    const int grp  = lane >> 3;             // 0..3: edge slot
    const int col  = lane & 7;              // uint4 (8 halves) within 64-half row

    int beg = __ldg(&g_rowptr[n]);
    int end = beg + __ldg(&g_cnt_in[n]);    // unordered-bucket CSR

    const uint4* t16 = (const uint4*)tin;
    float a0 = 0.f, a1 = 0.f, a2 = 0.f, a3 = 0.f;
    float a4 = 0.f, a5 = 0.f, a6 = 0.f, a7 = 0.f;

    for (int e = beg; e < end; e += 8) {
        int sv = N_NODES;                                   // dummy zero row
        if (lane < 8 && e + lane < end) sv = __ldg(&g_srcsrt[e + lane]);
        int s0 = __shfl_sync(0xFFFFFFFFu, sv, grp);          // edges e+0..e+3
        int s1 = __shfl_sync(0xFFFFFFFFu, sv, 4 + grp);      // edges e+4..e+7
        uint4 v0 = __ldg(&t16[(size_t)s0 * 8 + col]);
        uint4 v1 = __ldg(&t16[(size_t)s1 * 8 + col]);
        // pair-add in fp16 (independent rounding noise), accumulate fp32
        __half2 p;
        float2 f;
        p = __hadd2(*(__half2*)&v0.x, *(__half2*)&v1.x);
        f = __half22float2(p); a0 += f.x; a1 += f.y;
        p = __hadd2(*(__half2*)&v0.y, *(__half2*)&v1.y);
        f = __half22float2(p); a2 += f.x; a3 += f.y;
        p = __hadd2(*(__half2*)&v0.z, *(__half2*)&v1.z);
        f = __half22float2(p); a4 += f.x; a5 += f.y;
        p = __hadd2(*(__half2*)&v0.w, *(__half2*)&v1.w);
        f = __half22float2(p); a6 += f.x; a7 += f.y;
    }

    // reduce across the 4 edge-groups (lanes sharing the same col)
#pragma unroll
    for (int off = 8; off <= 16; off <<= 1) {
        a0 += __shfl_xor_sync(0xFFFFFFFFu, a0, off);
        a1 += __shfl_xor_sync(0xFFFFFFFFu, a1, off);
        a2 += __shfl_xor_sync(0xFFFFFFFFu, a2, off);
        a3 += __shfl_xor_sync(0xFFFFFFFFu, a3, off);
        a4 += __shfl_xor_sync(0xFFFFFFFFu, a4, off);
        a5 += __shfl_xor_sync(0xFFFFFFFFu, a5, off);
        a6 += __shfl_xor_sync(0xFFFFFFFFu, a6, off);
        a7 += __shfl_xor_sync(0xFFFFFFFFu, a7, off);
    }

    if (lane < 8) {
        float nd = __ldg(&g_nd[n]);
        float r0, r1, r2, r3, r4, r5, r6, r7;
        if (MODE == 0) {
            r0 = a0 * nd; r1 = a1 * nd; r2 = a2 * nd; r3 = a3 * nd;
            r4 = a4 * nd; r5 = a5 * nd; r6 = a6 * nd; r7 = a7 * nd;
        } else {
            const float4* b4 = (const float4*)bias;
            float4 ba = b4[col * 2], bb = b4[col * 2 + 1];
            r0 = fmaxf(a0 * nd + ba.x, 0.f);
            r1 = fmaxf(a1 * nd + ba.y, 0.f);
            r2 = fmaxf(a2 * nd + ba.z, 0.f);
            r3 = fmaxf(a3 * nd + ba.w, 0.f);
            r4 = fmaxf(a4 * nd + bb.x, 0.f);
            r5 = fmaxf(a5 * nd + bb.y, 0.f);
            r6 = fmaxf(a6 * nd + bb.z, 0.f);
            r7 = fmaxf(a7 * nd + bb.w, 0.f);
            if (MODE == 1) {
                float ns = __ldg(&g_ns[n]);
                r0 *= ns; r1 *= ns; r2 *= ns; r3 *= ns;
                r4 *= ns; r5 *= ns; r6 *= ns; r7 *= ns;
            }
        }
        __half2 h0 = __float22half2_rn(make_float2(r0, r1));
        __half2 h1 = __float22half2_rn(make_float2(r2, r3));
        __half2 h2 = __float22half2_rn(make_float2(r4, r5));
        __half2 h3 = __float22half2_rn(make_float2(r6, r7));
        uint4 u;
        u.x = *(unsigned*)&h0; u.y = *(unsigned*)&h1;
        u.z = *(unsigned*)&h2; u.w = *(unsigned*)&h3;
        ((uint4*)outp)[(size_t)n * 8 + col] = u;
    }
}

// ---------------- graph pooling (graph_ids sorted, fp16 input) --------------------
__global__ void k_pool(const __half* __restrict__ h, const int* __restrict__ gid) {
    int f = threadIdx.x & 63;
    int r = threadIdx.x >> 6;
    int start = blockIdx.x * 512;
    int end = min(start + 512, N_NODES);
    float acc = 0.f;
    int cur = -1;
    for (int n = start + r; n < end; n += 4) {
        int g = gid[n];
        if (g != cur) {
            if (cur >= 0) atomicAdd(&g_hg[cur * 64 + f], acc);
            cur = g; acc = 0.f;
        }
        acc += __half2float(h[(size_t)n * 64 + f]);
    }
    if (cur >= 0) atomicAdd(&g_hg[cur * 64 + f], acc);
}

// ---------------- head: out = tanh(hg) @ Wd + bd ---------------------------------
__global__ void k_final(const float* __restrict__ Wd, const float* __restrict__ bd,
                        float* __restrict__ out) {
    int t = threadIdx.x;
    if (t >= N_GRAPHS * 10) return;
    int g = t / 10, c = t % 10;
    float acc = bd[c];
#pragma unroll 8
    for (int k = 0; k < 64; k++)
        acc += tanhf(g_hg[g * 64 + k]) * Wd[k * 10 + c];
    out[t] = acc;
}

// ---------------- host orchestration ----------------------------------------------
extern "C" void kernel_launch(void* const* d_in, const int* in_sizes, int n_in,
                              void* d_out, int out_size) {
    const float* in_feat = (const float*)d_in[0];
    const int*   src     = (const int*)  d_in[1];
    const int*   dst     = (const int*)  d_in[2];
    const int*   gid     = (const int*)  d_in[3];
    const float* W1 = (const float*)d_in[4];
    const float* b1 = (const float*)d_in[5];
    const float* W2 = (const float*)d_in[6];
    const float* b2 = (const float*)d_in[7];
    const float* W3 = (const float*)d_in[8];
    const float* b3 = (const float*)d_in[9];
    const float* Wd = (const float*)d_in[10];
    const float* bd = (const float*)d_in[11];
    float* out = (float*)d_out;

    float *p_ns;
    __half *p_th, *p_mh, *p_hh;
    __half2 *p_w1hi, *p_w1lo, *p_w2hi, *p_w2lo, *p_w3hi, *p_w3lo;
    cudaGetSymbolAddress((void**)&p_ns, g_ns);
    cudaGetSymbolAddress((void**)&p_th, g_th);
    cudaGetSymbolAddress((void**)&p_mh, g_mh);
    cudaGetSymbolAddress((void**)&p_hh, g_hh);
    cudaGetSymbolAddress((void**)&p_w1hi, g_w1hi);
    cudaGetSymbolAddress((void**)&p_w1lo, g_w1lo);
    cudaGetSymbolAddress((void**)&p_w2hi, g_w2hi);
    cudaGetSymbolAddress((void**)&p_w2lo, g_w2lo);
    cudaGetSymbolAddress((void**)&p_w3hi, g_w3hi);
    cudaGetSymbolAddress((void**)&p_w3lo, g_w3lo);

    // persistent side stream + events for capture fork-join (host objects only)
    static cudaStream_t s1 = nullptr;
    static cudaEvent_t evS = nullptr, evM = nullptr;
    if (s1 == nullptr) {
        cudaStreamCreateWithFlags(&s1, cudaStreamNonBlocking);
        cudaEventCreateWithFlags(&evS, cudaEventDisableTiming);
        cudaEventCreateWithFlags(&evM, cudaEventDisableTiming);
    }

    const int TPB = 256;
    const int E4_BLKS   = (N_EDGES / 4 + TPB - 1) / TPB;  // 3125
    const int GATH_BLKS = N_NODES / 8;                    // 12500 (exact)
    const int MM_BLKS   = (N_NODES + 127) / 128;          // 782

    const int SM1   = 128 * (128 + 8) * 2 + 2 * 64 * 65 * 4;  // layer-1 mm
    const int SM23  = 119552;                                  // fused mm2+mm3
    cudaFuncSetAttribute(k_mmtc<128, 64, false, false, false, true>,
                         cudaFuncAttributeMaxDynamicSharedMemorySize, SM1);
    cudaFuncSetAttribute(k_mm23,
                         cudaFuncAttributeMaxDynamicSharedMemorySize, SM23);

    // ---- launch 1: zero + wpack (fused) ----
    k_zero <<<NBLK, TPB>>>(W1, W2, W3);
    // ---- launch 2-3: CSR build ----
    k_hist <<<E4_BLKS, TPB>>>(src, dst);
    k_scanA<<<NBLK, TPB>>>();
    cudaEventRecord(evS, 0);

    // ---- launch 4 (side): layer-1 mm, overlaps k_fill ----
    cudaStreamWaitEvent(s1, evS, 0);
    k_mmtc<128, 64, false, false, false, true><<<MM_BLKS, TPB, SM1, s1>>>(
        in_feat, p_w1hi, p_w1lo, nullptr, nullptr, p_ns, p_th);
    cudaEventRecord(evM, s1);

    // ---- launch 5: bucket fill ----
    k_fill <<<E4_BLKS, TPB>>>(src, dst);
    cudaStreamWaitEvent(0, evM, 0);        // join before gather1

    // ---- launch 6: Layer 1 gather (ncu -s 5 -c 1 profiles THIS) ----
    k_gather<1><<<GATH_BLKS, TPB>>>(p_th, b1, p_mh);

    // ---- Layer 2 gather: agg*nd -> fp16 g_th ----
    k_gather<0><<<GATH_BLKS, TPB>>>(p_mh, nullptr, p_th);

    // ---- fused mm2+mm3 ----
    k_mm23<<<MM_BLKS, TPB, SM23>>>(p_th, p_w2hi, p_w2lo, b2, p_ns,
                                   p_w3hi, p_w3lo, p_hh);

    // ---- Layer 3 gather ----
    k_gather<2><<<GATH_BLKS, TPB>>>(p_hh, b3, p_mh);

    // ---- pooling + head ----
    k_pool <<<(N_NODES + 511) / 512, TPB>>>(p_mh, gid);
    k_final<<<1, N_GRAPHS * 10>>>(Wd, bd, out);
}

// round 15
// speedup vs baseline: 1.1174x; 1.1174x over previous
#include <cuda_runtime.h>
#include <cuda_fp16.h>
#include <math.h>

#define N_NODES 100000
#define N_EDGES 3200000
#define N_GRAPHS 64
#define NBLK 391                    // ceil(N_NODES/256)

// ---------------- scratch (device globals; no runtime allocation) ------------
__device__ __align__(16) int     g_cnt_in [N_NODES];
__device__ __align__(16) int     g_cnt_out[N_NODES];
__device__ __align__(16) int     g_rank   [N_EDGES];
__device__ __align__(16) int     g_rowptr [N_NODES + 1];
__device__              int      g_ctr;
__device__ __align__(16) int     g_srcsrt [N_EDGES];
__device__ __align__(16) float   g_ns [N_NODES];
__device__ __align__(16) float   g_nd [N_NODES];
__device__ __align__(16) __half  g_th[((size_t)N_NODES + 1) * 64]; // messages (+dummy)
__device__ __align__(16) __half  g_mh[((size_t)N_NODES + 1) * 64]; // activations (+dummy)
__device__ __align__(16) __half  g_hh[((size_t)N_NODES + 1) * 64]; // L3 messages (+dummy)
__device__ __align__(16) float   g_hg[N_GRAPHS * 64];
// packed fp16 weights in padded smem layout: (K2 half2-rows) x (DOUT+1)
__device__ __align__(16) __half2 g_w1[64 * 65];
__device__ __align__(16) __half2 g_w2[32 * 129];
__device__ __align__(16) __half2 g_w3[64 * 65];

// ---------------- pack W helper --------------------------------------------------
__device__ __forceinline__ void wpack_one(const float* __restrict__ W,
                                          __half2* dst, int i, int DOUT) {
    int k = i / DOUT, n = i % DOUT;
    int WROW = DOUT + 1;
    ((__half*)dst)[((k >> 1) * WROW + n) * 2 + (k & 1)] = __float2half_rn(__ldg(&W[i]));
}

// ---------------- zero + weight packing (fused: one launch) ----------------------
__global__ void k_zero(const float* __restrict__ W1, const float* __restrict__ W2,
                       const float* __restrict__ W3) {
    int i = blockIdx.x * blockDim.x + threadIdx.x;
    if (i < N_NODES) { g_cnt_in[i] = 0; g_cnt_out[i] = 0; }
    if (i < N_GRAPHS * 64) g_hg[i] = 0.f;
    if (i == 0) g_ctr = 0;
    if (i < 32) {                                  // dummy zero rows for gather tails
        ((int*)(g_th + (size_t)N_NODES * 64))[i] = 0;
        ((int*)(g_mh + (size_t)N_NODES * 64))[i] = 0;
        ((int*)(g_hh + (size_t)N_NODES * 64))[i] = 0;
    }
    if (i < 8192)            wpack_one(W1, g_w1, i, 64);
    else if (i < 16384)      wpack_one(W2, g_w2, i - 8192, 128);
    else if (i < 24576)      wpack_one(W3, g_w3, i - 16384, 64);
}

// ---------------- degree histograms + free edge ranks (4 edges/thread) ----------
__global__ void k_hist(const int* __restrict__ src, const int* __restrict__ dst) {
    int i = blockIdx.x * blockDim.x + threadIdx.x;     // over N_EDGES/4
    if (i * 4 >= N_EDGES) return;
    int4 s4 = __ldg((const int4*)src + i);
    int4 d4 = __ldg((const int4*)dst + i);
    int4 r4;
    r4.x = atomicAdd(&g_cnt_in[d4.x], 1);
    r4.y = atomicAdd(&g_cnt_in[d4.y], 1);
    r4.z = atomicAdd(&g_cnt_in[d4.z], 1);
    r4.w = atomicAdd(&g_cnt_in[d4.w], 1);
    ((int4*)g_rank)[i] = r4;
    atomicAdd(&g_cnt_out[s4.x], 1);
    atomicAdd(&g_cnt_out[s4.y], 1);
    atomicAdd(&g_cnt_out[s4.z], 1);
    atomicAdd(&g_cnt_out[s4.w], 1);
}

// ---------------- single-pass "scan": disjoint (unordered) buckets + norms -------
__global__ void k_scanA() {
    __shared__ int sh[256];
    __shared__ int sbase;
    int i = blockIdx.x * 256 + threadIdx.x;
    int v = (i < N_NODES) ? g_cnt_in[i] : 0;
    sh[threadIdx.x] = v;
    __syncthreads();
#pragma unroll
    for (int off = 1; off < 256; off <<= 1) {
        int t = (threadIdx.x >= off) ? sh[threadIdx.x - off] : 0;
        __syncthreads();
        sh[threadIdx.x] += t;
        __syncthreads();
    }
    if (threadIdx.x == 255) sbase = atomicAdd(&g_ctr, sh[255]);
    __syncthreads();
    if (i < N_NODES) {
        g_rowptr[i] = sbase + sh[threadIdx.x] - v;       // exclusive within block
        g_ns[i] = rsqrtf(fmaxf((float)g_cnt_out[i], 1.f));
        g_nd[i] = rsqrtf(fmaxf((float)g_cnt_in [i], 1.f));
    }
}

// ---------------- bucket fill: atomic-free (4 edges/thread) ---------------------
__global__ void k_fill(const int* __restrict__ src, const int* __restrict__ dst) {
    int i = blockIdx.x * blockDim.x + threadIdx.x;
    if (i * 4 >= N_EDGES) return;
    int4 s4 = __ldg((const int4*)src + i);
    int4 d4 = __ldg((const int4*)dst + i);
    int4 r4 = ((const int4*)g_rank)[i];
    g_srcsrt[__ldg(&g_rowptr[d4.x]) + r4.x] = s4.x;
    g_srcsrt[__ldg(&g_rowptr[d4.y]) + r4.y] = s4.y;
    g_srcsrt[__ldg(&g_rowptr[d4.z]) + r4.z] = s4.z;
    g_srcsrt[__ldg(&g_rowptr[d4.w]) + r4.w] = s4.w;
}

// ---------------- tensor-core matmul (packed fp16 W) — layer 1 only --------------
template <int DIN, int DOUT, bool RELU, bool HASBIAS, bool SCALE, bool IN32>
__global__ void k_mmtc(const void* __restrict__ Xv,
                       const __half2* __restrict__ Wp,
                       const float* __restrict__ bias, const float* __restrict__ scale,
                       const float* __restrict__ inscale, __half* __restrict__ out) {
    constexpr int XROW = DIN + 8;
    constexpr int WROW = DOUT + 1;
    constexpr int K2   = DIN / 2;
    constexpr int NT   = DOUT / 8;
    constexpr int WU4  = K2 * WROW / 4;      // uint4 per packed matrix
    extern __shared__ char smem[];
    __half*  sX = (__half*)smem;
    __half2* sW = (__half2*)(smem + 128 * XROW * 2);

    const int tid = threadIdx.x;
    const int wid = tid >> 5, lane = tid & 31;
    const int g = lane >> 2, tig = lane & 3;

    {
        const uint4* w4 = (const uint4*)Wp;
        uint4* sw4 = (uint4*)sW;
        for (int i = tid; i < WU4; i += 256) sw4[i] = __ldg(&w4[i]);
    }

    const int base = blockIdx.x * 128;
    constexpr int QPR = DIN / 8;
    for (int i = tid; i < 128 * QPR; i += 256) {
        int r = i / QPR, q = i % QPR;
        int n = base + r;
        uint4 v = make_uint4(0u, 0u, 0u, 0u);
        if (n < N_NODES) {
            if (IN32) {
                const float* X = (const float*)Xv;
                float s = __ldg(&inscale[n]);
                const float4* p = (const float4*)(X + (size_t)n * DIN) + q * 2;
                float4 u0 = __ldg(p), u1 = __ldg(p + 1);
                __half2 h0 = __float22half2_rn(make_float2(u0.x * s, u0.y * s));
                __half2 h1 = __float22half2_rn(make_float2(u0.z * s, u0.w * s));
                __half2 h2 = __float22half2_rn(make_float2(u1.x * s, u1.y * s));
                __half2 h3 = __float22half2_rn(make_float2(u1.z * s, u1.w * s));
                v.x = *(unsigned*)&h0; v.y = *(unsigned*)&h1;
                v.z = *(unsigned*)&h2; v.w = *(unsigned*)&h3;
            } else {
                const __half* X = (const __half*)Xv;
                v = __ldg((const uint4*)(X + (size_t)n * DIN) + q);
            }
        }
        *(uint4*)(sX + r * XROW + q * 8) = v;
    }
    __syncthreads();

    float c[NT][4];
#pragma unroll
    for (int t = 0; t < NT; t++) { c[t][0] = c[t][1] = c[t][2] = c[t][3] = 0.f; }

    const __half* xw = sX + wid * 16 * XROW;
#pragma unroll
    for (int k0 = 0; k0 < DIN; k0 += 16) {
        const __half* ap = xw + (size_t)(lane & 15) * XROW + k0 + ((lane >> 4) << 3);
        unsigned aaddr = (unsigned)__cvta_generic_to_shared(ap);
        unsigned a0, a1, a2, a3;
        asm volatile("ldmatrix.sync.aligned.m8n8.x4.shared.b16 {%0,%1,%2,%3}, [%4];"
                     : "=r"(a0), "=r"(a1), "=r"(a2), "=r"(a3) : "r"(aaddr));
#pragma unroll
        for (int t = 0; t < NT; t++) {
            unsigned b0 = *(const unsigned*)&sW[(k0 / 2 + tig)     * WROW + t * 8 + g];
            unsigned b1 = *(const unsigned*)&sW[(k0 / 2 + 4 + tig) * WROW + t * 8 + g];
            asm volatile("mma.sync.aligned.m16n8k16.row.col.f32.f16.f16.f32 "
                         "{%0,%1,%2,%3}, {%4,%5,%6,%7}, {%8,%9}, {%0,%1,%2,%3};"
                         : "+f"(c[t][0]), "+f"(c[t][1]), "+f"(c[t][2]), "+f"(c[t][3])
                         : "r"(a0), "r"(a1), "r"(a2), "r"(a3), "r"(b0), "r"(b1));
        }
    }

    int n0 = base + wid * 16 + g;
    int n1 = n0 + 8;
    float s0 = 1.f, s1 = 1.f;
    if (SCALE) {
        if (n0 < N_NODES) s0 = __ldg(&scale[n0]);
        if (n1 < N_NODES) s1 = __ldg(&scale[n1]);
    }
#pragma unroll
    for (int t = 0; t < NT; t++) {
        int j0 = t * 8 + tig * 2;
        float bb0 = 0.f, bb1 = 0.f;
        if (HASBIAS) { bb0 = __ldg(&bias[j0]); bb1 = __ldg(&bias[j0 + 1]); }
        if (n0 < N_NODES) {
            float r0 = c[t][0] + bb0, r1 = c[t][1] + bb1;
            if (RELU) { r0 = fmaxf(r0, 0.f); r1 = fmaxf(r1, 0.f); }
            r0 *= s0; r1 *= s0;
            __half2 h = __float22half2_rn(make_float2(r0, r1));
            *(unsigned*)(out + (size_t)n0 * DOUT + j0) = *(unsigned*)&h;
        }
        if (n1 < N_NODES) {
            float r0 = c[t][2] + bb0, r1 = c[t][3] + bb1;
            if (RELU) { r0 = fmaxf(r0, 0.f); r1 = fmaxf(r1, 0.f); }
            r0 *= s1; r1 *= s1;
            __half2 h = __float22half2_rn(make_float2(r0, r1));
            *(unsigned*)(out + (size_t)n1 * DOUT + j0) = *(unsigned*)&h;
        }
    }
}

// ---------------- fused mm2+mm3: out = (relu(X@W2 + b2) * ns) @ W3 ---------------
// smem: sX 0..18432 | sW2 18432..34944 | sH 34944..69760 | sW3 69760..86400
__global__ void k_mm23(const __half* __restrict__ X,
                       const __half2* __restrict__ W2p, const float* __restrict__ b2,
                       const float* __restrict__ ns,
                       const __half2* __restrict__ W3p, __half* __restrict__ out) {
    extern __shared__ char smem[];
    __half*  sX  = (__half*)smem;
    __half2* sW2 = (__half2*)(smem + 18432);
    __half*  sH  = (__half*)(smem + 34944);
    __half2* sW3 = (__half2*)(smem + 69760);

    const int tid = threadIdx.x;
    const int wid = tid >> 5, lane = tid & 31;
    const int g = lane >> 2, tig = lane & 3;
    const int base = blockIdx.x * 128;

    // W2: 32*129 half2 = 1032 uint4; W3: 64*65 half2 = 1040 uint4
    {
        const uint4* a = (const uint4*)W2p;
        uint4* sa = (uint4*)sW2;
        for (int i = tid; i < 1032; i += 256) sa[i] = __ldg(&a[i]);
        const uint4* c4 = (const uint4*)W3p;
        uint4* sc = (uint4*)sW3;
        for (int i = tid; i < 1040; i += 256) sc[i] = __ldg(&c4[i]);
    }

    for (int i = tid; i < 128 * 8; i += 256) {
        int r = i / 8, q = i % 8;
        int n = base + r;
        uint4 v = make_uint4(0u, 0u, 0u, 0u);
        if (n < N_NODES) v = __ldg((const uint4*)(X + (size_t)n * 64) + q);
        *(uint4*)(sX + r * 72 + q * 8) = v;
    }
    __syncthreads();

    float c[16][4];
#pragma unroll
    for (int t = 0; t < 16; t++) { c[t][0] = c[t][1] = c[t][2] = c[t][3] = 0.f; }

    {
        const __half* xw = sX + wid * 16 * 72;
#pragma unroll
        for (int k0 = 0; k0 < 64; k0 += 16) {
            const __half* ap = xw + (size_t)(lane & 15) * 72 + k0 + ((lane >> 4) << 3);
            unsigned aaddr = (unsigned)__cvta_generic_to_shared(ap);
            unsigned a0, a1, a2, a3;
            asm volatile("ldmatrix.sync.aligned.m8n8.x4.shared.b16 {%0,%1,%2,%3}, [%4];"
                         : "=r"(a0), "=r"(a1), "=r"(a2), "=r"(a3) : "r"(aaddr));
#pragma unroll
            for (int t = 0; t < 16; t++) {
                unsigned b0 = *(const unsigned*)&sW2[(k0 / 2 + tig)     * 129 + t * 8 + g];
                unsigned b1 = *(const unsigned*)&sW2[(k0 / 2 + 4 + tig) * 129 + t * 8 + g];
                asm volatile("mma.sync.aligned.m16n8k16.row.col.f32.f16.f16.f32 "
                             "{%0,%1,%2,%3}, {%4,%5,%6,%7}, {%8,%9}, {%0,%1,%2,%3};"
                             : "+f"(c[t][0]), "+f"(c[t][1]), "+f"(c[t][2]), "+f"(c[t][3])
                             : "r"(a0), "r"(a1), "r"(a2), "r"(a3), "r"(b0), "r"(b1));
            }
        }
    }

    {
        int ln0 = wid * 16 + g;
        int ln1 = ln0 + 8;
        int n0 = base + ln0, n1 = base + ln1;
        float s0 = (n0 < N_NODES) ? __ldg(&ns[n0]) : 0.f;
        float s1 = (n1 < N_NODES) ? __ldg(&ns[n1]) : 0.f;
#pragma unroll
        for (int t = 0; t < 16; t++) {
            int j0 = t * 8 + tig * 2;
            float bb0 = __ldg(&b2[j0]), bb1 = __ldg(&b2[j0 + 1]);
            float r0 = fmaxf(c[t][0] + bb0, 0.f) * s0;
            float r1 = fmaxf(c[t][1] + bb1, 0.f) * s0;
            float r2 = fmaxf(c[t][2] + bb0, 0.f) * s1;
            float r3 = fmaxf(c[t][3] + bb1, 0.f) * s1;
            __half2 h0 = __float22half2_rn(make_float2(r0, r1));
            __half2 h1 = __float22half2_rn(make_float2(r2, r3));
            *(unsigned*)(sH + ln0 * 136 + j0) = *(unsigned*)&h0;
            *(unsigned*)(sH + ln1 * 136 + j0) = *(unsigned*)&h1;
        }
    }
    __syncthreads();

    float c2[8][4];
#pragma unroll
    for (int t = 0; t < 8; t++) { c2[t][0] = c2[t][1] = c2[t][2] = c2[t][3] = 0.f; }

    {
        const __half* xw = sH + wid * 16 * 136;
#pragma unroll
        for (int k0 = 0; k0 < 128; k0 += 16) {
            const __half* ap = xw + (size_t)(lane & 15) * 136 + k0 + ((lane >> 4) << 3);
            unsigned aaddr = (unsigned)__cvta_generic_to_shared(ap);
            unsigned a0, a1, a2, a3;
            asm volatile("ldmatrix.sync.aligned.m8n8.x4.shared.b16 {%0,%1,%2,%3}, [%4];"
                         : "=r"(a0), "=r"(a1), "=r"(a2), "=r"(a3) : "r"(aaddr));
#pragma unroll
            for (int t = 0; t < 8; t++) {
                unsigned b0 = *(const unsigned*)&sW3[(k0 / 2 + tig)     * 65 + t * 8 + g];
                unsigned b1 = *(const unsigned*)&sW3[(k0 / 2 + 4 + tig) * 65 + t * 8 + g];
                asm volatile("mma.sync.aligned.m16n8k16.row.col.f32.f16.f16.f32 "
                             "{%0,%1,%2,%3}, {%4,%5,%6,%7}, {%8,%9}, {%0,%1,%2,%3};"
                             : "+f"(c2[t][0]), "+f"(c2[t][1]), "+f"(c2[t][2]), "+f"(c2[t][3])
                             : "r"(a0), "r"(a1), "r"(a2), "r"(a3), "r"(b0), "r"(b1));
            }
        }
    }

    {
        int n0 = base + wid * 16 + g;
        int n1 = n0 + 8;
#pragma unroll
        for (int t = 0; t < 8; t++) {
            int j0 = t * 8 + tig * 2;
            if (n0 < N_NODES) {
                __half2 h = __float22half2_rn(make_float2(c2[t][0], c2[t][1]));
                *(unsigned*)(out + (size_t)n0 * 64 + j0) = *(unsigned*)&h;
            }
            if (n1 < N_NODES) {
                __half2 h = __float22half2_rn(make_float2(c2[t][2], c2[t][3]));
                *(unsigned*)(out + (size_t)n1 * 64 + j0) = *(unsigned*)&h;
            }
        }
    }
}

// ---------------- CSR gather: warp/node, 8 lanes/edge, LDG.128 (fp16) -------------
// MODE 0: out(fp16) = sum * nd                  (L2 mm input, nd folded)
// MODE 1: out(fp16) = relu(sum*nd + b) * ns     (L1 output)
// MODE 2: out(fp16) = relu(sum*nd + b)          (L3 output, pool input)
template <int MODE>
__global__ void k_gather(const __half* __restrict__ tin, const float* __restrict__ bias,
                         __half* __restrict__ outp) {
    const int lane = threadIdx.x & 31;
    const int wid  = threadIdx.x >> 5;
    const int n    = blockIdx.x * 8 + wid;
    const int grp  = lane >> 3;             // 0..3: edge slot
    const int col  = lane & 7;              // uint4 (8 halves) within 64-half row

    int beg = __ldg(&g_rowptr[n]);
    int end = beg + __ldg(&g_cnt_in[n]);    // unordered-bucket CSR

    const uint4* t16 = (const uint4*)tin;
    float a0 = 0.f, a1 = 0.f, a2 = 0.f, a3 = 0.f;
    float a4 = 0.f, a5 = 0.f, a6 = 0.f, a7 = 0.f;

    for (int e = beg; e < end; e += 8) {
        int sv = N_NODES;                                   // dummy zero row
        if (lane < 8 && e + lane < end) sv = __ldg(&g_srcsrt[e + lane]);
        int s0 = __shfl_sync(0xFFFFFFFFu, sv, grp);          // edges e+0..e+3
        int s1 = __shfl_sync(0xFFFFFFFFu, sv, 4 + grp);      // edges e+4..e+7
        uint4 v0 = __ldg(&t16[(size_t)s0 * 8 + col]);
        uint4 v1 = __ldg(&t16[(size_t)s1 * 8 + col]);
        float2 f;
        f = __half22float2(*(__half2*)&v0.x); a0 += f.x; a1 += f.y;
        f = __half22float2(*(__half2*)&v0.y); a2 += f.x; a3 += f.y;
        f = __half22float2(*(__half2*)&v0.z); a4 += f.x; a5 += f.y;
        f = __half22float2(*(__half2*)&v0.w); a6 += f.x; a7 += f.y;
        f = __half22float2(*(__half2*)&v1.x); a0 += f.x; a1 += f.y;
        f = __half22float2(*(__half2*)&v1.y); a2 += f.x; a3 += f.y;
        f = __half22float2(*(__half2*)&v1.z); a4 += f.x; a5 += f.y;
        f = __half22float2(*(__half2*)&v1.w); a6 += f.x; a7 += f.y;
    }

    // reduce across the 4 edge-groups (lanes sharing the same col)
#pragma unroll
    for (int off = 8; off <= 16; off <<= 1) {
        a0 += __shfl_xor_sync(0xFFFFFFFFu, a0, off);
        a1 += __shfl_xor_sync(0xFFFFFFFFu, a1, off);
        a2 += __shfl_xor_sync(0xFFFFFFFFu, a2, off);
        a3 += __shfl_xor_sync(0xFFFFFFFFu, a3, off);
        a4 += __shfl_xor_sync(0xFFFFFFFFu, a4, off);
        a5 += __shfl_xor_sync(0xFFFFFFFFu, a5, off);
        a6 += __shfl_xor_sync(0xFFFFFFFFu, a6, off);
        a7 += __shfl_xor_sync(0xFFFFFFFFu, a7, off);
    }

    if (lane < 8) {
        float nd = __ldg(&g_nd[n]);
        float r0, r1, r2, r3, r4, r5, r6, r7;
        if (MODE == 0) {
            r0 = a0 * nd; r1 = a1 * nd; r2 = a2 * nd; r3 = a3 * nd;
            r4 = a4 * nd; r5 = a5 * nd; r6 = a6 * nd; r7 = a7 * nd;
        } else {
            const float4* b4 = (const float4*)bias;
            float4 ba = b4[col * 2], bb = b4[col * 2 + 1];
            r0 = fmaxf(a0 * nd + ba.x, 0.f);
            r1 = fmaxf(a1 * nd + ba.y, 0.f);
            r2 = fmaxf(a2 * nd + ba.z, 0.f);
            r3 = fmaxf(a3 * nd + ba.w, 0.f);
            r4 = fmaxf(a4 * nd + bb.x, 0.f);
            r5 = fmaxf(a5 * nd + bb.y, 0.f);
            r6 = fmaxf(a6 * nd + bb.z, 0.f);
            r7 = fmaxf(a7 * nd + bb.w, 0.f);
            if (MODE == 1) {
                float ns = __ldg(&g_ns[n]);
                r0 *= ns; r1 *= ns; r2 *= ns; r3 *= ns;
                r4 *= ns; r5 *= ns; r6 *= ns; r7 *= ns;
            }
        }
        __half2 h0 = __float22half2_rn(make_float2(r0, r1));
        __half2 h1 = __float22half2_rn(make_float2(r2, r3));
        __half2 h2 = __float22half2_rn(make_float2(r4, r5));
        __half2 h3 = __float22half2_rn(make_float2(r6, r7));
        uint4 u;
        u.x = *(unsigned*)&h0; u.y = *(unsigned*)&h1;
        u.z = *(unsigned*)&h2; u.w = *(unsigned*)&h3;
        ((uint4*)outp)[(size_t)n * 8 + col] = u;
    }
}

// ---------------- graph pooling (graph_ids sorted, fp16 input) --------------------
__global__ void k_pool(const __half* __restrict__ h, const int* __restrict__ gid) {
    int f = threadIdx.x & 63;
    int r = threadIdx.x >> 6;
    int start = blockIdx.x * 512;
    int end = min(start + 512, N_NODES);
    float acc = 0.f;
    int cur = -1;
    for (int n = start + r; n < end; n += 4) {
        int g = gid[n];
        if (g != cur) {
            if (cur >= 0) atomicAdd(&g_hg[cur * 64 + f], acc);
            cur = g; acc = 0.f;
        }
        acc += __half2float(h[(size_t)n * 64 + f]);
    }
    if (cur >= 0) atomicAdd(&g_hg[cur * 64 + f], acc);
}

// ---------------- head: out = tanh(hg) @ Wd + bd ---------------------------------
__global__ void k_final(const float* __restrict__ Wd, const float* __restrict__ bd,
                        float* __restrict__ out) {
    int t = threadIdx.x;
    if (t >= N_GRAPHS * 10) return;
    int g = t / 10, c = t % 10;
    float acc = bd[c];
#pragma unroll 8
    for (int k = 0; k < 64; k++)
        acc += tanhf(g_hg[g * 64 + k]) * Wd[k * 10 + c];
    out[t] = acc;
}

// ---------------- host orchestration ----------------------------------------------
extern "C" void kernel_launch(void* const* d_in, const int* in_sizes, int n_in,
                              void* d_out, int out_size) {
    const float* in_feat = (const float*)d_in[0];
    const int*   src     = (const int*)  d_in[1];
    const int*   dst     = (const int*)  d_in[2];
    const int*   gid     = (const int*)  d_in[3];
    const float* W1 = (const float*)d_in[4];
    const float* b1 = (const float*)d_in[5];
    const float* W2 = (const float*)d_in[6];
    const float* b2 = (const float*)d_in[7];
    const float* W3 = (const float*)d_in[8];
    const float* b3 = (const float*)d_in[9];
    const float* Wd = (const float*)d_in[10];
    const float* bd = (const float*)d_in[11];
    float* out = (float*)d_out;

    float *p_ns;
    __half *p_th, *p_mh, *p_hh;
    __half2 *p_w1, *p_w2, *p_w3;
    cudaGetSymbolAddress((void**)&p_ns, g_ns);
    cudaGetSymbolAddress((void**)&p_th, g_th);
    cudaGetSymbolAddress((void**)&p_mh, g_mh);
    cudaGetSymbolAddress((void**)&p_hh, g_hh);
    cudaGetSymbolAddress((void**)&p_w1, g_w1);
    cudaGetSymbolAddress((void**)&p_w2, g_w2);
    cudaGetSymbolAddress((void**)&p_w3, g_w3);

    // persistent side stream + events for capture fork-join (host objects only)
    static cudaStream_t s1 = nullptr;
    static cudaEvent_t evS = nullptr, evM = nullptr;
    if (s1 == nullptr) {
        cudaStreamCreateWithFlags(&s1, cudaStreamNonBlocking);
        cudaEventCreateWithFlags(&evS, cudaEventDisableTiming);
        cudaEventCreateWithFlags(&evM, cudaEventDisableTiming);
    }

    const int TPB = 256;
    const int E4_BLKS   = (N_EDGES / 4 + TPB - 1) / TPB;  // 3125
    const int GATH_BLKS = N_NODES / 8;                    // 12500 (exact)
    const int MM_BLKS   = (N_NODES + 127) / 128;          // 782

    const int SM1  = 128 * (128 + 8) * 2 + 64 * 65 * 4;   // 51456
    const int SM23 = 86400;
    cudaFuncSetAttribute(k_mmtc<128, 64, false, false, false, true>,
                         cudaFuncAttributeMaxDynamicSharedMemorySize, SM1);
    cudaFuncSetAttribute(k_mm23,
                         cudaFuncAttributeMaxDynamicSharedMemorySize, SM23);

    // ---- launch 1: zero + wpack (fused) ----
    k_zero <<<NBLK, TPB>>>(W1, W2, W3);
    // ---- CSR build ----
    k_hist <<<E4_BLKS, TPB>>>(src, dst);
    k_scanA<<<NBLK, TPB>>>();
    cudaEventRecord(evS, 0);

    // ---- side stream: layer-1 mm, overlaps k_fill ----
    cudaStreamWaitEvent(s1, evS, 0);
    k_mmtc<128, 64, false, false, false, true><<<MM_BLKS, TPB, SM1, s1>>>(
        in_feat, p_w1, nullptr, nullptr, p_ns, p_th);
    cudaEventRecord(evM, s1);

    // ---- main stream: bucket fill ----
    k_fill <<<E4_BLKS, TPB>>>(src, dst);
    cudaStreamWaitEvent(0, evM, 0);        // join before gather1

    // ---- Layer 1 gather ----
    k_gather<1><<<GATH_BLKS, TPB>>>(p_th, b1, p_mh);

    // ---- Layer 2 gather ----
    k_gather<0><<<GATH_BLKS, TPB>>>(p_mh, nullptr, p_th);

    // ---- fused mm2+mm3 ----
    k_mm23<<<MM_BLKS, TPB, SM23>>>(p_th, p_w2, b2, p_ns, p_w3, p_hh);

    // ---- Layer 3 gather ----
    k_gather<2><<<GATH_BLKS, TPB>>>(p_hh, b3, p_mh);

    // ---- pooling + head ----
    k_pool <<<(N_NODES + 511) / 512, TPB>>>(p_mh, gid);
    k_final<<<1, N_GRAPHS * 10>>>(Wd, bd, out);
}

// round 16
// speedup vs baseline: 1.2051x; 1.0785x over previous
#include <cuda_runtime.h>
#include <cuda_fp16.h>
#include <math.h>

#define N_NODES 100000
#define N_EDGES 3200000
#define N_GRAPHS 64
#define NBLK 391                    // ceil(N_NODES/256)

// ---------------- scratch (device globals; no runtime allocation) ------------
__device__ __align__(16) int     g_cnt_in [N_NODES];
__device__ __align__(16) int     g_cnt_out[N_NODES];
__device__ __align__(16) int     g_rank   [N_EDGES];
__device__ __align__(16) int     g_rowptr [N_NODES + 1];
__device__              int      g_ctr;
__device__ __align__(16) int     g_srcsrt [N_EDGES];
__device__ __align__(16) float   g_ns [N_NODES];
__device__ __align__(16) float   g_nd [N_NODES];
__device__ __align__(16) __half  g_th[((size_t)N_NODES + 1) * 64]; // messages (+dummy)
__device__ __align__(16) __half  g_mh[((size_t)N_NODES + 1) * 64]; // activations (+dummy)
__device__ __align__(16) __half  g_hh[((size_t)N_NODES + 1) * 64]; // L3 messages (+dummy)
__device__ __align__(16) float   g_hg[N_GRAPHS * 64];
// packed fp16 weights, padded layout: (K2 half2-rows) x (DOUT+8)  [conflict-free]
__device__ __align__(16) __half2 g_w1[64 * 72];
__device__ __align__(16) __half2 g_w2[32 * 136];
__device__ __align__(16) __half2 g_w3[64 * 72];

// ---------------- pack W helper (WROW = DOUT+8) -----------------------------------
__device__ __forceinline__ void wpack_one(const float* __restrict__ W,
                                          __half2* dst, int i, int DOUT) {
    int k = i / DOUT, n = i % DOUT;
    int WROW = DOUT + 8;
    ((__half*)dst)[((k >> 1) * WROW + n) * 2 + (k & 1)] = __float2half_rn(__ldg(&W[i]));
}

// ---------------- zero + weight packing (fused: one launch) ----------------------
__global__ void k_zero(const float* __restrict__ W1, const float* __restrict__ W2,
                       const float* __restrict__ W3) {
    int i = blockIdx.x * blockDim.x + threadIdx.x;
    if (i < N_NODES) { g_cnt_in[i] = 0; g_cnt_out[i] = 0; }
    if (i < N_GRAPHS * 64) g_hg[i] = 0.f;
    if (i == 0) g_ctr = 0;
    if (i < 32) {                                  // dummy zero rows for gather tails
        ((int*)(g_th + (size_t)N_NODES * 64))[i] = 0;
        ((int*)(g_mh + (size_t)N_NODES * 64))[i] = 0;
        ((int*)(g_hh + (size_t)N_NODES * 64))[i] = 0;
    }
    if (i < 8192)            wpack_one(W1, g_w1, i, 64);
    else if (i < 16384)      wpack_one(W2, g_w2, i - 8192, 128);
    else if (i < 24576)      wpack_one(W3, g_w3, i - 16384, 64);
}

// ---------------- degree histograms + free edge ranks (4 edges/thread) ----------
__global__ void k_hist(const int* __restrict__ src, const int* __restrict__ dst) {
    int i = blockIdx.x * blockDim.x + threadIdx.x;     // over N_EDGES/4
    if (i * 4 >= N_EDGES) return;
    int4 s4 = __ldg((const int4*)src + i);
    int4 d4 = __ldg((const int4*)dst + i);
    int4 r4;
    r4.x = atomicAdd(&g_cnt_in[d4.x], 1);
    r4.y = atomicAdd(&g_cnt_in[d4.y], 1);
    r4.z = atomicAdd(&g_cnt_in[d4.z], 1);
    r4.w = atomicAdd(&g_cnt_in[d4.w], 1);
    ((int4*)g_rank)[i] = r4;
    atomicAdd(&g_cnt_out[s4.x], 1);
    atomicAdd(&g_cnt_out[s4.y], 1);
    atomicAdd(&g_cnt_out[s4.z], 1);
    atomicAdd(&g_cnt_out[s4.w], 1);
}

// ---------------- single-pass "scan": disjoint (unordered) buckets + norms -------
__global__ void k_scanA() {
    __shared__ int sh[256];
    __shared__ int sbase;
    int i = blockIdx.x * 256 + threadIdx.x;
    int v = (i < N_NODES) ? g_cnt_in[i] : 0;
    sh[threadIdx.x] = v;
    __syncthreads();
#pragma unroll
    for (int off = 1; off < 256; off <<= 1) {
        int t = (threadIdx.x >= off) ? sh[threadIdx.x - off] : 0;
        __syncthreads();
        sh[threadIdx.x] += t;
        __syncthreads();
    }
    if (threadIdx.x == 255) sbase = atomicAdd(&g_ctr, sh[255]);
    __syncthreads();
    if (i < N_NODES) {
        g_rowptr[i] = sbase + sh[threadIdx.x] - v;       // exclusive within block
        g_ns[i] = rsqrtf(fmaxf((float)g_cnt_out[i], 1.f));
        g_nd[i] = rsqrtf(fmaxf((float)g_cnt_in [i], 1.f));
    }
}

// ---------------- bucket fill: atomic-free (4 edges/thread) ---------------------
__global__ void k_fill(const int* __restrict__ src, const int* __restrict__ dst) {
    int i = blockIdx.x * blockDim.x + threadIdx.x;
    if (i * 4 >= N_EDGES) return;
    int4 s4 = __ldg((const int4*)src + i);
    int4 d4 = __ldg((const int4*)dst + i);
    int4 r4 = ((const int4*)g_rank)[i];
    g_srcsrt[__ldg(&g_rowptr[d4.x]) + r4.x] = s4.x;
    g_srcsrt[__ldg(&g_rowptr[d4.y]) + r4.y] = s4.y;
    g_srcsrt[__ldg(&g_rowptr[d4.z]) + r4.z] = s4.z;
    g_srcsrt[__ldg(&g_rowptr[d4.w]) + r4.w] = s4.w;
}

// ---------------- tensor-core matmul (packed fp16 W, conflict-free) --------------
template <int DIN, int DOUT, bool RELU, bool HASBIAS, bool SCALE, bool IN32>
__global__ void k_mmtc(const void* __restrict__ Xv,
                       const __half2* __restrict__ Wp,
                       const float* __restrict__ bias, const float* __restrict__ scale,
                       const float* __restrict__ inscale, __half* __restrict__ out) {
    constexpr int XROW = DIN + 8;
    constexpr int WROW = DOUT + 8;
    constexpr int K2   = DIN / 2;
    constexpr int NT   = DOUT / 8;
    constexpr int WU4  = K2 * WROW / 4;      // uint4 per packed matrix
    extern __shared__ char smem[];
    __half*  sX = (__half*)smem;
    __half2* sW = (__half2*)(smem + 128 * XROW * 2);

    const int tid = threadIdx.x;
    const int wid = tid >> 5, lane = tid & 31;
    const int g = lane >> 2, tig = lane & 3;

    {
        const uint4* w4 = (const uint4*)Wp;
        uint4* sw4 = (uint4*)sW;
        for (int i = tid; i < WU4; i += 256) sw4[i] = __ldg(&w4[i]);
    }

    const int base = blockIdx.x * 128;
    constexpr int QPR = DIN / 8;
    for (int i = tid; i < 128 * QPR; i += 256) {
        int r = i / QPR, q = i % QPR;
        int n = base + r;
        uint4 v = make_uint4(0u, 0u, 0u, 0u);
        if (n < N_NODES) {
            if (IN32) {
                const float* X = (const float*)Xv;
                float s = __ldg(&inscale[n]);
                const float4* p = (const float4*)(X + (size_t)n * DIN) + q * 2;
                float4 u0 = __ldg(p), u1 = __ldg(p + 1);
                __half2 h0 = __float22half2_rn(make_float2(u0.x * s, u0.y * s));
                __half2 h1 = __float22half2_rn(make_float2(u0.z * s, u0.w * s));
                __half2 h2 = __float22half2_rn(make_float2(u1.x * s, u1.y * s));
                __half2 h3 = __float22half2_rn(make_float2(u1.z * s, u1.w * s));
                v.x = *(unsigned*)&h0; v.y = *(unsigned*)&h1;
                v.z = *(unsigned*)&h2; v.w = *(unsigned*)&h3;
            } else {
                const __half* X = (const __half*)Xv;
                v = __ldg((const uint4*)(X + (size_t)n * DIN) + q);
            }
        }
        *(uint4*)(sX + r * XROW + q * 8) = v;
    }
    __syncthreads();

    float c[NT][4];
#pragma unroll
    for (int t = 0; t < NT; t++) { c[t][0] = c[t][1] = c[t][2] = c[t][3] = 0.f; }

    const __half* xw = sX + wid * 16 * XROW;
#pragma unroll
    for (int k0 = 0; k0 < DIN; k0 += 16) {
        const __half* ap = xw + (size_t)(lane & 15) * XROW + k0 + ((lane >> 4) << 3);
        unsigned aaddr = (unsigned)__cvta_generic_to_shared(ap);
        unsigned a0, a1, a2, a3;
        asm volatile("ldmatrix.sync.aligned.m8n8.x4.shared.b16 {%0,%1,%2,%3}, [%4];"
                     : "=r"(a0), "=r"(a1), "=r"(a2), "=r"(a3) : "r"(aaddr));
#pragma unroll
        for (int t = 0; t < NT; t++) {
            unsigned b0 = *(const unsigned*)&sW[(k0 / 2 + tig)     * WROW + t * 8 + g];
            unsigned b1 = *(const unsigned*)&sW[(k0 / 2 + 4 + tig) * WROW + t * 8 + g];
            asm volatile("mma.sync.aligned.m16n8k16.row.col.f32.f16.f16.f32 "
                         "{%0,%1,%2,%3}, {%4,%5,%6,%7}, {%8,%9}, {%0,%1,%2,%3};"
                         : "+f"(c[t][0]), "+f"(c[t][1]), "+f"(c[t][2]), "+f"(c[t][3])
                         : "r"(a0), "r"(a1), "r"(a2), "r"(a3), "r"(b0), "r"(b1));
        }
    }

    int n0 = base + wid * 16 + g;
    int n1 = n0 + 8;
    float s0 = 1.f, s1 = 1.f;
    if (SCALE) {
        if (n0 < N_NODES) s0 = __ldg(&scale[n0]);
        if (n1 < N_NODES) s1 = __ldg(&scale[n1]);
    }
#pragma unroll
    for (int t = 0; t < NT; t++) {
        int j0 = t * 8 + tig * 2;
        float bb0 = 0.f, bb1 = 0.f;
        if (HASBIAS) { bb0 = __ldg(&bias[j0]); bb1 = __ldg(&bias[j0 + 1]); }
        if (n0 < N_NODES) {
            float r0 = c[t][0] + bb0, r1 = c[t][1] + bb1;
            if (RELU) { r0 = fmaxf(r0, 0.f); r1 = fmaxf(r1, 0.f); }
            r0 *= s0; r1 *= s0;
            __half2 h = __float22half2_rn(make_float2(r0, r1));
            *(unsigned*)(out + (size_t)n0 * DOUT + j0) = *(unsigned*)&h;
        }
        if (n1 < N_NODES) {
            float r0 = c[t][2] + bb0, r1 = c[t][3] + bb1;
            if (RELU) { r0 = fmaxf(r0, 0.f); r1 = fmaxf(r1, 0.f); }
            r0 *= s1; r1 *= s1;
            __half2 h = __float22half2_rn(make_float2(r0, r1));
            *(unsigned*)(out + (size_t)n1 * DOUT + j0) = *(unsigned*)&h;
        }
    }
}

// ---------------- fused mm2+mm3: out = (relu(X@W2 + b2) * ns) @ W3 ---------------
// smem: sX 0..18432 | sW2 18432..35840 (32x136 half2) | sH 35840..70656 (128x136 h)
//       sW3 70656..89088 (64x72 half2)
__global__ void k_mm23(const __half* __restrict__ X,
                       const __half2* __restrict__ W2p, const float* __restrict__ b2,
                       const float* __restrict__ ns,
                       const __half2* __restrict__ W3p, __half* __restrict__ out) {
    extern __shared__ char smem[];
    __half*  sX  = (__half*)smem;
    __half2* sW2 = (__half2*)(smem + 18432);
    __half*  sH  = (__half*)(smem + 35840);
    __half2* sW3 = (__half2*)(smem + 70656);

    const int tid = threadIdx.x;
    const int wid = tid >> 5, lane = tid & 31;
    const int g = lane >> 2, tig = lane & 3;
    const int base = blockIdx.x * 128;

    // W2: 32*136 half2 = 17408B = 1088 uint4; W3: 64*72 half2 = 18432B = 1152 uint4
    {
        const uint4* a = (const uint4*)W2p;
        uint4* sa = (uint4*)sW2;
        for (int i = tid; i < 1088; i += 256) sa[i] = __ldg(&a[i]);
        const uint4* c4 = (const uint4*)W3p;
        uint4* sc = (uint4*)sW3;
        for (int i = tid; i < 1152; i += 256) sc[i] = __ldg(&c4[i]);
    }

    for (int i = tid; i < 128 * 8; i += 256) {
        int r = i / 8, q = i % 8;
        int n = base + r;
        uint4 v = make_uint4(0u, 0u, 0u, 0u);
        if (n < N_NODES) v = __ldg((const uint4*)(X + (size_t)n * 64) + q);
        *(uint4*)(sX + r * 72 + q * 8) = v;
    }
    __syncthreads();

    float c[16][4];
#pragma unroll
    for (int t = 0; t < 16; t++) { c[t][0] = c[t][1] = c[t][2] = c[t][3] = 0.f; }

    {
        const __half* xw = sX + wid * 16 * 72;
#pragma unroll
        for (int k0 = 0; k0 < 64; k0 += 16) {
            const __half* ap = xw + (size_t)(lane & 15) * 72 + k0 + ((lane >> 4) << 3);
            unsigned aaddr = (unsigned)__cvta_generic_to_shared(ap);
            unsigned a0, a1, a2, a3;
            asm volatile("ldmatrix.sync.aligned.m8n8.x4.shared.b16 {%0,%1,%2,%3}, [%4];"
                         : "=r"(a0), "=r"(a1), "=r"(a2), "=r"(a3) : "r"(aaddr));
#pragma unroll
            for (int t = 0; t < 16; t++) {
                unsigned b0 = *(const unsigned*)&sW2[(k0 / 2 + tig)     * 136 + t * 8 + g];
                unsigned b1 = *(const unsigned*)&sW2[(k0 / 2 + 4 + tig) * 136 + t * 8 + g];
                asm volatile("mma.sync.aligned.m16n8k16.row.col.f32.f16.f16.f32 "
                             "{%0,%1,%2,%3}, {%4,%5,%6,%7}, {%8,%9}, {%0,%1,%2,%3};"
                             : "+f"(c[t][0]), "+f"(c[t][1]), "+f"(c[t][2]), "+f"(c[t][3])
                             : "r"(a0), "r"(a1), "r"(a2), "r"(a3), "r"(b0), "r"(b1));
            }
        }
    }

    {
        int ln0 = wid * 16 + g;
        int ln1 = ln0 + 8;
        int n0 = base + ln0, n1 = base + ln1;
        float s0 = (n0 < N_NODES) ? __ldg(&ns[n0]) : 0.f;
        float s1 = (n1 < N_NODES) ? __ldg(&ns[n1]) : 0.f;
#pragma unroll
        for (int t = 0; t < 16; t++) {
            int j0 = t * 8 + tig * 2;
            float bb0 = __ldg(&b2[j0]), bb1 = __ldg(&b2[j0 + 1]);
            float r0 = fmaxf(c[t][0] + bb0, 0.f) * s0;
            float r1 = fmaxf(c[t][1] + bb1, 0.f) * s0;
            float r2 = fmaxf(c[t][2] + bb0, 0.f) * s1;
            float r3 = fmaxf(c[t][3] + bb1, 0.f) * s1;
            __half2 h0 = __float22half2_rn(make_float2(r0, r1));
            __half2 h1 = __float22half2_rn(make_float2(r2, r3));
            *(unsigned*)(sH + ln0 * 136 + j0) = *(unsigned*)&h0;
            *(unsigned*)(sH + ln1 * 136 + j0) = *(unsigned*)&h1;
        }
    }
    __syncthreads();

    float c2[8][4];
#pragma unroll
    for (int t = 0; t < 8; t++) { c2[t][0] = c2[t][1] = c2[t][2] = c2[t][3] = 0.f; }

    {
        const __half* xw = sH + wid * 16 * 136;
#pragma unroll
        for (int k0 = 0; k0 < 128; k0 += 16) {
            const __half* ap = xw + (size_t)(lane & 15) * 136 + k0 + ((lane >> 4) << 3);
            unsigned aaddr = (unsigned)__cvta_generic_to_shared(ap);
            unsigned a0, a1, a2, a3;
            asm volatile("ldmatrix.sync.aligned.m8n8.x4.shared.b16 {%0,%1,%2,%3}, [%4];"
                         : "=r"(a0), "=r"(a1), "=r"(a2), "=r"(a3) : "r"(aaddr));
#pragma unroll
            for (int t = 0; t < 8; t++) {
                unsigned b0 = *(const unsigned*)&sW3[(k0 / 2 + tig)     * 72 + t * 8 + g];
                unsigned b1 = *(const unsigned*)&sW3[(k0 / 2 + 4 + tig) * 72 + t * 8 + g];
                asm volatile("mma.sync.aligned.m16n8k16.row.col.f32.f16.f16.f32 "
                             "{%0,%1,%2,%3}, {%4,%5,%6,%7}, {%8,%9}, {%0,%1,%2,%3};"
                             : "+f"(c2[t][0]), "+f"(c2[t][1]), "+f"(c2[t][2]), "+f"(c2[t][3])
                             : "r"(a0), "r"(a1), "r"(a2), "r"(a3), "r"(b0), "r"(b1));
            }
        }
    }

    {
        int n0 = base + wid * 16 + g;
        int n1 = n0 + 8;
#pragma unroll
        for (int t = 0; t < 8; t++) {
            int j0 = t * 8 + tig * 2;
            if (n0 < N_NODES) {
                __half2 h = __float22half2_rn(make_float2(c2[t][0], c2[t][1]));
                *(unsigned*)(out + (size_t)n0 * 64 + j0) = *(unsigned*)&h;
            }
            if (n1 < N_NODES) {
                __half2 h = __float22half2_rn(make_float2(c2[t][2], c2[t][3]));
                *(unsigned*)(out + (size_t)n1 * 64 + j0) = *(unsigned*)&h;
            }
        }
    }
}

// ---------------- CSR gather: warp/node, 8 lanes/edge, LDG.128 (fp16) -------------
// MODE 0: out(fp16) = sum * nd                  (L2 mm input, nd folded)
// MODE 1: out(fp16) = relu(sum*nd + b) * ns     (L1 output)
// MODE 2: out(fp16) = relu(sum*nd + b)          (L3 output, pool input)
template <int MODE>
__global__ void k_gather(const __half* __restrict__ tin, const float* __restrict__ bias,
                         __half* __restrict__ outp) {
    const int lane = threadIdx.x & 31;
    const int wid  = threadIdx.x >> 5;
    const int n    = blockIdx.x * 8 + wid;
    const int grp  = lane >> 3;             // 0..3: edge slot
    const int col  = lane & 7;              // uint4 (8 halves) within 64-half row

    int beg = __ldg(&g_rowptr[n]);
    int end = beg + __ldg(&g_cnt_in[n]);    // unordered-bucket CSR

    const uint4* t16 = (const uint4*)tin;
    float a0 = 0.f, a1 = 0.f, a2 = 0.f, a3 = 0.f;
    float a4 = 0.f, a5 = 0.f, a6 = 0.f, a7 = 0.f;

    for (int e = beg; e < end; e += 8) {
        int sv = N_NODES;                                   // dummy zero row
        if (lane < 8 && e + lane < end) sv = __ldg(&g_srcsrt[e + lane]);
        int s0 = __shfl_sync(0xFFFFFFFFu, sv, grp);          // edges e+0..e+3
        int s1 = __shfl_sync(0xFFFFFFFFu, sv, 4 + grp);      // edges e+4..e+7
        uint4 v0 = __ldg(&t16[(size_t)s0 * 8 + col]);
        uint4 v1 = __ldg(&t16[(size_t)s1 * 8 + col]);
        float2 f;
        f = __half22float2(*(__half2*)&v0.x); a0 += f.x; a1 += f.y;
        f = __half22float2(*(__half2*)&v0.y); a2 += f.x; a3 += f.y;
        f = __half22float2(*(__half2*)&v0.z); a4 += f.x; a5 += f.y;
        f = __half22float2(*(__half2*)&v0.w); a6 += f.x; a7 += f.y;
        f = __half22float2(*(__half2*)&v1.x); a0 += f.x; a1 += f.y;
        f = __half22float2(*(__half2*)&v1.y); a2 += f.x; a3 += f.y;
        f = __half22float2(*(__half2*)&v1.z); a4 += f.x; a5 += f.y;
        f = __half22float2(*(__half2*)&v1.w); a6 += f.x; a7 += f.y;
    }

    // reduce across the 4 edge-groups (lanes sharing the same col)
#pragma unroll
    for (int off = 8; off <= 16; off <<= 1) {
        a0 += __shfl_xor_sync(0xFFFFFFFFu, a0, off);
        a1 += __shfl_xor_sync(0xFFFFFFFFu, a1, off);
        a2 += __shfl_xor_sync(0xFFFFFFFFu, a2, off);
        a3 += __shfl_xor_sync(0xFFFFFFFFu, a3, off);
        a4 += __shfl_xor_sync(0xFFFFFFFFu, a4, off);
        a5 += __shfl_xor_sync(0xFFFFFFFFu, a5, off);
        a6 += __shfl_xor_sync(0xFFFFFFFFu, a6, off);
        a7 += __shfl_xor_sync(0xFFFFFFFFu, a7, off);
    }

    if (lane < 8) {
        float nd = __ldg(&g_nd[n]);
        float r0, r1, r2, r3, r4, r5, r6, r7;
        if (MODE == 0) {
            r0 = a0 * nd; r1 = a1 * nd; r2 = a2 * nd; r3 = a3 * nd;
            r4 = a4 * nd; r5 = a5 * nd; r6 = a6 * nd; r7 = a7 * nd;
        } else {
            const float4* b4 = (const float4*)bias;
            float4 ba = b4[col * 2], bb = b4[col * 2 + 1];
            r0 = fmaxf(a0 * nd + ba.x, 0.f);
            r1 = fmaxf(a1 * nd + ba.y, 0.f);
            r2 = fmaxf(a2 * nd + ba.z, 0.f);
            r3 = fmaxf(a3 * nd + ba.w, 0.f);
            r4 = fmaxf(a4 * nd + bb.x, 0.f);
            r5 = fmaxf(a5 * nd + bb.y, 0.f);
            r6 = fmaxf(a6 * nd + bb.z, 0.f);
            r7 = fmaxf(a7 * nd + bb.w, 0.f);
            if (MODE == 1) {
                float ns = __ldg(&g_ns[n]);
                r0 *= ns; r1 *= ns; r2 *= ns; r3 *= ns;
                r4 *= ns; r5 *= ns; r6 *= ns; r7 *= ns;
            }
        }
        __half2 h0 = __float22half2_rn(make_float2(r0, r1));
        __half2 h1 = __float22half2_rn(make_float2(r2, r3));
        __half2 h2 = __float22half2_rn(make_float2(r4, r5));
        __half2 h3 = __float22half2_rn(make_float2(r6, r7));
        uint4 u;
        u.x = *(unsigned*)&h0; u.y = *(unsigned*)&h1;
        u.z = *(unsigned*)&h2; u.w = *(unsigned*)&h3;
        ((uint4*)outp)[(size_t)n * 8 + col] = u;
    }
}

// ---------------- graph pooling (graph_ids sorted, fp16 input) --------------------
__global__ void k_pool(const __half* __restrict__ h, const int* __restrict__ gid) {
    int f = threadIdx.x & 63;
    int r = threadIdx.x >> 6;
    int start = blockIdx.x * 512;
    int end = min(start + 512, N_NODES);
    float acc = 0.f;
    int cur = -1;
    for (int n = start + r; n < end; n += 4) {
        int g = gid[n];
        if (g != cur) {
            if (cur >= 0) atomicAdd(&g_hg[cur * 64 + f], acc);
            cur = g; acc = 0.f;
        }
        acc += __half2float(h[(size_t)n * 64 + f]);
    }
    if (cur >= 0) atomicAdd(&g_hg[cur * 64 + f], acc);
}

// ---------------- head: out = tanh(hg) @ Wd + bd ---------------------------------
__global__ void k_final(const float* __restrict__ Wd, const float* __restrict__ bd,
                        float* __restrict__ out) {
    int t = threadIdx.x;
    if (t >= N_GRAPHS * 10) return;
    int g = t / 10, c = t % 10;
    float acc = bd[c];
#pragma unroll 8
    for (int k = 0; k < 64; k++)
        acc += tanhf(g_hg[g * 64 + k]) * Wd[k * 10 + c];
    out[t] = acc;
}

// ---------------- host orchestration ----------------------------------------------
extern "C" void kernel_launch(void* const* d_in, const int* in_sizes, int n_in,
                              void* d_out, int out_size) {
    const float* in_feat = (const float*)d_in[0];
    const int*   src     = (const int*)  d_in[1];
    const int*   dst     = (const int*)  d_in[2];
    const int*   gid     = (const int*)  d_in[3];
    const float* W1 = (const float*)d_in[4];
    const float* b1 = (const float*)d_in[5];
    const float* W2 = (const float*)d_in[6];
    const float* b2 = (const float*)d_in[7];
    const float* W3 = (const float*)d_in[8];
    const float* b3 = (const float*)d_in[9];
    const float* Wd = (const float*)d_in[10];
    const float* bd = (const float*)d_in[11];
    float* out = (float*)d_out;

    float *p_ns;
    __half *p_th, *p_mh, *p_hh;
    __half2 *p_w1, *p_w2, *p_w3;
    cudaGetSymbolAddress((void**)&p_ns, g_ns);
    cudaGetSymbolAddress((void**)&p_th, g_th);
    cudaGetSymbolAddress((void**)&p_mh, g_mh);
    cudaGetSymbolAddress((void**)&p_hh, g_hh);
    cudaGetSymbolAddress((void**)&p_w1, g_w1);
    cudaGetSymbolAddress((void**)&p_w2, g_w2);
    cudaGetSymbolAddress((void**)&p_w3, g_w3);

    // persistent side stream + events for capture fork-join (host objects only)
    static cudaStream_t s1 = nullptr;
    static cudaEvent_t evS = nullptr, evM = nullptr;
    if (s1 == nullptr) {
        cudaStreamCreateWithFlags(&s1, cudaStreamNonBlocking);
        cudaEventCreateWithFlags(&evS, cudaEventDisableTiming);
        cudaEventCreateWithFlags(&evM, cudaEventDisableTiming);
    }

    const int TPB = 256;
    const int E4_BLKS   = (N_EDGES / 4 + TPB - 1) / TPB;  // 3125
    const int GATH_BLKS = N_NODES / 8;                    // 12500 (exact)
    const int MM_BLKS   = (N_NODES + 127) / 128;          // 782

    const int SM1  = 128 * 136 * 2 + 64 * 72 * 4;         // 34816 + 18432 = 53248
    const int SM23 = 89088;
    cudaFuncSetAttribute(k_mmtc<128, 64, false, false, false, true>,
                         cudaFuncAttributeMaxDynamicSharedMemorySize, SM1);
    cudaFuncSetAttribute(k_mm23,
                         cudaFuncAttributeMaxDynamicSharedMemorySize, SM23);

    // ---- launch 1: zero + wpack (fused) ----
    k_zero <<<NBLK, TPB>>>(W1, W2, W3);
    // ---- CSR build ----
    k_hist <<<E4_BLKS, TPB>>>(src, dst);
    k_scanA<<<NBLK, TPB>>>();
    cudaEventRecord(evS, 0);

    // ---- side stream: layer-1 mm, overlaps k_fill ----
    cudaStreamWaitEvent(s1, evS, 0);
    k_mmtc<128, 64, false, false, false, true><<<MM_BLKS, TPB, SM1, s1>>>(
        in_feat, p_w1, nullptr, nullptr, p_ns, p_th);
    cudaEventRecord(evM, s1);

    // ---- main stream: bucket fill ----
    k_fill <<<E4_BLKS, TPB>>>(src, dst);
    cudaStreamWaitEvent(0, evM, 0);        // join before gather1

    // ---- Layer 1 gather ----
    k_gather<1><<<GATH_BLKS, TPB>>>(p_th, b1, p_mh);

    // ---- Layer 2 gather ----
    k_gather<0><<<GATH_BLKS, TPB>>>(p_mh, nullptr, p_th);

    // ---- fused mm2+mm3 ----
    k_mm23<<<MM_BLKS, TPB, SM23>>>(p_th, p_w2, b2, p_ns, p_w3, p_hh);

    // ---- Layer 3 gather ----
    k_gather<2><<<GATH_BLKS, TPB>>>(p_hh, b3, p_mh);

    // ---- pooling + head ----
    k_pool <<<(N_NODES + 511) / 512, TPB>>>(p_mh, gid);
    k_final<<<1, N_GRAPHS * 10>>>(Wd, bd, out);
}

// round 17
// speedup vs baseline: 1.2409x; 1.0297x over previous
#include <cuda_runtime.h>
#include <cuda_fp16.h>
#include <math.h>

#define N_NODES 100000
#define N_EDGES 3200000
#define N_GRAPHS 64
#define NBLK 391                    // ceil(N_NODES/256)

// ---------------- scratch (device globals; no runtime allocation) ------------
__device__ __align__(16) int     g_cnt_in [N_NODES];
__device__ __align__(16) int     g_cnt_out[N_NODES];
__device__ __align__(16) int     g_rank   [N_EDGES];
__device__ __align__(16) int     g_rowptr [N_NODES + 1];
__device__              int      g_ctr;
__device__ __align__(16) int     g_srcsrt [N_EDGES + 16];   // +pad for prefetch
__device__ __align__(16) float   g_ns [N_NODES];
__device__ __align__(16) float   g_nd [N_NODES];
__device__ __align__(16) __half  g_th[((size_t)N_NODES + 1) * 64]; // messages (+dummy)
__device__ __align__(16) __half  g_mh[((size_t)N_NODES + 1) * 64]; // activations (+dummy)
__device__ __align__(16) __half  g_hh[((size_t)N_NODES + 1) * 64]; // L3 messages (+dummy)
__device__ __align__(16) float   g_hg[N_GRAPHS * 64];
// packed fp16 weights, padded layout: (K2 half2-rows) x (DOUT+8)  [conflict-free]
__device__ __align__(16) __half2 g_w1[64 * 72];
__device__ __align__(16) __half2 g_w2[32 * 136];
__device__ __align__(16) __half2 g_w3[64 * 72];

// ---------------- pack W helper (WROW = DOUT+8) -----------------------------------
__device__ __forceinline__ void wpack_one(const float* __restrict__ W,
                                          __half2* dst, int i, int DOUT) {
    int k = i / DOUT, n = i % DOUT;
    int WROW = DOUT + 8;
    ((__half*)dst)[((k >> 1) * WROW + n) * 2 + (k & 1)] = __float2half_rn(__ldg(&W[i]));
}

// ---------------- zero + weight packing (fused: one launch) ----------------------
__global__ void k_zero(const float* __restrict__ W1, const float* __restrict__ W2,
                       const float* __restrict__ W3) {
    int i = blockIdx.x * blockDim.x + threadIdx.x;
    if (i < N_NODES) { g_cnt_in[i] = 0; g_cnt_out[i] = 0; }
    if (i < N_GRAPHS * 64) g_hg[i] = 0.f;
    if (i == 0) g_ctr = 0;
    if (i < 32) {                                  // dummy zero rows for gather tails
        ((int*)(g_th + (size_t)N_NODES * 64))[i] = 0;
        ((int*)(g_mh + (size_t)N_NODES * 64))[i] = 0;
        ((int*)(g_hh + (size_t)N_NODES * 64))[i] = 0;
    }
    if (i < 16) g_srcsrt[N_EDGES + i] = N_NODES;   // prefetch pad -> dummy row
    if (i < 8192)            wpack_one(W1, g_w1, i, 64);
    else if (i < 16384)      wpack_one(W2, g_w2, i - 8192, 128);
    else if (i < 24576)      wpack_one(W3, g_w3, i - 16384, 64);
}

// ---------------- degree histograms + free edge ranks (4 edges/thread) ----------
__global__ void k_hist(const int* __restrict__ src, const int* __restrict__ dst) {
    int i = blockIdx.x * blockDim.x + threadIdx.x;     // over N_EDGES/4
    if (i * 4 >= N_EDGES) return;
    int4 s4 = __ldg((const int4*)src + i);
    int4 d4 = __ldg((const int4*)dst + i);
    int4 r4;
    r4.x = atomicAdd(&g_cnt_in[d4.x], 1);
    r4.y = atomicAdd(&g_cnt_in[d4.y], 1);
    r4.z = atomicAdd(&g_cnt_in[d4.z], 1);
    r4.w = atomicAdd(&g_cnt_in[d4.w], 1);
    ((int4*)g_rank)[i] = r4;
    atomicAdd(&g_cnt_out[s4.x], 1);
    atomicAdd(&g_cnt_out[s4.y], 1);
    atomicAdd(&g_cnt_out[s4.z], 1);
    atomicAdd(&g_cnt_out[s4.w], 1);
}

// ---------------- single-pass "scan": disjoint (unordered) buckets + norms -------
__global__ void k_scanA() {
    __shared__ int sh[256];
    __shared__ int sbase;
    int i = blockIdx.x * 256 + threadIdx.x;
    int v = (i < N_NODES) ? g_cnt_in[i] : 0;
    sh[threadIdx.x] = v;
    __syncthreads();
#pragma unroll
    for (int off = 1; off < 256; off <<= 1) {
        int t = (threadIdx.x >= off) ? sh[threadIdx.x - off] : 0;
        __syncthreads();
        sh[threadIdx.x] += t;
        __syncthreads();
    }
    if (threadIdx.x == 255) sbase = atomicAdd(&g_ctr, sh[255]);
    __syncthreads();
    if (i < N_NODES) {
        g_rowptr[i] = sbase + sh[threadIdx.x] - v;       // exclusive within block
        g_ns[i] = rsqrtf(fmaxf((float)g_cnt_out[i], 1.f));
        g_nd[i] = rsqrtf(fmaxf((float)g_cnt_in [i], 1.f));
    }
}

// ---------------- bucket fill: atomic-free (4 edges/thread) ---------------------
__global__ void k_fill(const int* __restrict__ src, const int* __restrict__ dst) {
    int i = blockIdx.x * blockDim.x + threadIdx.x;
    if (i * 4 >= N_EDGES) return;
    int4 s4 = __ldg((const int4*)src + i);
    int4 d4 = __ldg((const int4*)dst + i);
    int4 r4 = ((const int4*)g_rank)[i];
    g_srcsrt[__ldg(&g_rowptr[d4.x]) + r4.x] = s4.x;
    g_srcsrt[__ldg(&g_rowptr[d4.y]) + r4.y] = s4.y;
    g_srcsrt[__ldg(&g_rowptr[d4.z]) + r4.z] = s4.z;
    g_srcsrt[__ldg(&g_rowptr[d4.w]) + r4.w] = s4.w;
}

// ---------------- tensor-core matmul (packed fp16 W, conflict-free) --------------
template <int DIN, int DOUT, bool RELU, bool HASBIAS, bool SCALE, bool IN32>
__global__ void k_mmtc(const void* __restrict__ Xv,
                       const __half2* __restrict__ Wp,
                       const float* __restrict__ bias, const float* __restrict__ scale,
                       const float* __restrict__ inscale, __half* __restrict__ out) {
    constexpr int XROW = DIN + 8;
    constexpr int WROW = DOUT + 8;
    constexpr int K2   = DIN / 2;
    constexpr int NT   = DOUT / 8;
    constexpr int WU4  = K2 * WROW / 4;      // uint4 per packed matrix
    extern __shared__ char smem[];
    __half*  sX = (__half*)smem;
    __half2* sW = (__half2*)(smem + 128 * XROW * 2);

    const int tid = threadIdx.x;
    const int wid = tid >> 5, lane = tid & 31;
    const int g = lane >> 2, tig = lane & 3;

    {
        const uint4* w4 = (const uint4*)Wp;
        uint4* sw4 = (uint4*)sW;
        for (int i = tid; i < WU4; i += 256) sw4[i] = __ldg(&w4[i]);
    }

    const int base = blockIdx.x * 128;
    constexpr int QPR = DIN / 8;
    for (int i = tid; i < 128 * QPR; i += 256) {
        int r = i / QPR, q = i % QPR;
        int n = base + r;
        uint4 v = make_uint4(0u, 0u, 0u, 0u);
        if (n < N_NODES) {
            if (IN32) {
                const float* X = (const float*)Xv;
                float s = __ldg(&inscale[n]);
                const float4* p = (const float4*)(X + (size_t)n * DIN) + q * 2;
                float4 u0 = __ldg(p), u1 = __ldg(p + 1);
                __half2 h0 = __float22half2_rn(make_float2(u0.x * s, u0.y * s));
                __half2 h1 = __float22half2_rn(make_float2(u0.z * s, u0.w * s));
                __half2 h2 = __float22half2_rn(make_float2(u1.x * s, u1.y * s));
                __half2 h3 = __float22half2_rn(make_float2(u1.z * s, u1.w * s));
                v.x = *(unsigned*)&h0; v.y = *(unsigned*)&h1;
                v.z = *(unsigned*)&h2; v.w = *(unsigned*)&h3;
            } else {
                const __half* X = (const __half*)Xv;
                v = __ldg((const uint4*)(X + (size_t)n * DIN) + q);
            }
        }
        *(uint4*)(sX + r * XROW + q * 8) = v;
    }
    __syncthreads();

    float c[NT][4];
#pragma unroll
    for (int t = 0; t < NT; t++) { c[t][0] = c[t][1] = c[t][2] = c[t][3] = 0.f; }

    const __half* xw = sX + wid * 16 * XROW;
#pragma unroll
    for (int k0 = 0; k0 < DIN; k0 += 16) {
        const __half* ap = xw + (size_t)(lane & 15) * XROW + k0 + ((lane >> 4) << 3);
        unsigned aaddr = (unsigned)__cvta_generic_to_shared(ap);
        unsigned a0, a1, a2, a3;
        asm volatile("ldmatrix.sync.aligned.m8n8.x4.shared.b16 {%0,%1,%2,%3}, [%4];"
                     : "=r"(a0), "=r"(a1), "=r"(a2), "=r"(a3) : "r"(aaddr));
#pragma unroll
        for (int t = 0; t < NT; t++) {
            unsigned b0 = *(const unsigned*)&sW[(k0 / 2 + tig)     * WROW + t * 8 + g];
            unsigned b1 = *(const unsigned*)&sW[(k0 / 2 + 4 + tig) * WROW + t * 8 + g];
            asm volatile("mma.sync.aligned.m16n8k16.row.col.f32.f16.f16.f32 "
                         "{%0,%1,%2,%3}, {%4,%5,%6,%7}, {%8,%9}, {%0,%1,%2,%3};"
                         : "+f"(c[t][0]), "+f"(c[t][1]), "+f"(c[t][2]), "+f"(c[t][3])
                         : "r"(a0), "r"(a1), "r"(a2), "r"(a3), "r"(b0), "r"(b1));
        }
    }

    int n0 = base + wid * 16 + g;
    int n1 = n0 + 8;
    float s0 = 1.f, s1 = 1.f;
    if (SCALE) {
        if (n0 < N_NODES) s0 = __ldg(&scale[n0]);
        if (n1 < N_NODES) s1 = __ldg(&scale[n1]);
    }
#pragma unroll
    for (int t = 0; t < NT; t++) {
        int j0 = t * 8 + tig * 2;
        float bb0 = 0.f, bb1 = 0.f;
        if (HASBIAS) { bb0 = __ldg(&bias[j0]); bb1 = __ldg(&bias[j0 + 1]); }
        if (n0 < N_NODES) {
            float r0 = c[t][0] + bb0, r1 = c[t][1] + bb1;
            if (RELU) { r0 = fmaxf(r0, 0.f); r1 = fmaxf(r1, 0.f); }
            r0 *= s0; r1 *= s0;
            __half2 h = __float22half2_rn(make_float2(r0, r1));
            *(unsigned*)(out + (size_t)n0 * DOUT + j0) = *(unsigned*)&h;
        }
        if (n1 < N_NODES) {
            float r0 = c[t][2] + bb0, r1 = c[t][3] + bb1;
            if (RELU) { r0 = fmaxf(r0, 0.f); r1 = fmaxf(r1, 0.f); }
            r0 *= s1; r1 *= s1;
            __half2 h = __float22half2_rn(make_float2(r0, r1));
            *(unsigned*)(out + (size_t)n1 * DOUT + j0) = *(unsigned*)&h;
        }
    }
}

// ---------------- fused mm2+mm3: out = (relu(X@W2 + b2) * ns) @ W3 ---------------
// smem: sX 0..18432 | sW2 18432..35840 (32x136 half2) | sH 35840..70656 (128x136 h)
//       sW3 70656..89088 (64x72 half2)
__global__ void k_mm23(const __half* __restrict__ X,
                       const __half2* __restrict__ W2p, const float* __restrict__ b2,
                       const float* __restrict__ ns,
                       const __half2* __restrict__ W3p, __half* __restrict__ out) {
    extern __shared__ char smem[];
    __half*  sX  = (__half*)smem;
    __half2* sW2 = (__half2*)(smem + 18432);
    __half*  sH  = (__half*)(smem + 35840);
    __half2* sW3 = (__half2*)(smem + 70656);

    const int tid = threadIdx.x;
    const int wid = tid >> 5, lane = tid & 31;
    const int g = lane >> 2, tig = lane & 3;
    const int base = blockIdx.x * 128;

    {
        const uint4* a = (const uint4*)W2p;
        uint4* sa = (uint4*)sW2;
        for (int i = tid; i < 1088; i += 256) sa[i] = __ldg(&a[i]);
        const uint4* c4 = (const uint4*)W3p;
        uint4* sc = (uint4*)sW3;
        for (int i = tid; i < 1152; i += 256) sc[i] = __ldg(&c4[i]);
    }

    for (int i = tid; i < 128 * 8; i += 256) {
        int r = i / 8, q = i % 8;
        int n = base + r;
        uint4 v = make_uint4(0u, 0u, 0u, 0u);
        if (n < N_NODES) v = __ldg((const uint4*)(X + (size_t)n * 64) + q);
        *(uint4*)(sX + r * 72 + q * 8) = v;
    }
    __syncthreads();

    float c[16][4];
#pragma unroll
    for (int t = 0; t < 16; t++) { c[t][0] = c[t][1] = c[t][2] = c[t][3] = 0.f; }

    {
        const __half* xw = sX + wid * 16 * 72;
#pragma unroll
        for (int k0 = 0; k0 < 64; k0 += 16) {
            const __half* ap = xw + (size_t)(lane & 15) * 72 + k0 + ((lane >> 4) << 3);
            unsigned aaddr = (unsigned)__cvta_generic_to_shared(ap);
            unsigned a0, a1, a2, a3;
            asm volatile("ldmatrix.sync.aligned.m8n8.x4.shared.b16 {%0,%1,%2,%3}, [%4];"
                         : "=r"(a0), "=r"(a1), "=r"(a2), "=r"(a3) : "r"(aaddr));
#pragma unroll
            for (int t = 0; t < 16; t++) {
                unsigned b0 = *(const unsigned*)&sW2[(k0 / 2 + tig)     * 136 + t * 8 + g];
                unsigned b1 = *(const unsigned*)&sW2[(k0 / 2 + 4 + tig) * 136 + t * 8 + g];
                asm volatile("mma.sync.aligned.m16n8k16.row.col.f32.f16.f16.f32 "
                             "{%0,%1,%2,%3}, {%4,%5,%6,%7}, {%8,%9}, {%0,%1,%2,%3};"
                             : "+f"(c[t][0]), "+f"(c[t][1]), "+f"(c[t][2]), "+f"(c[t][3])
                             : "r"(a0), "r"(a1), "r"(a2), "r"(a3), "r"(b0), "r"(b1));
            }
        }
    }

    {
        int ln0 = wid * 16 + g;
        int ln1 = ln0 + 8;
        int n0 = base + ln0, n1 = base + ln1;
        float s0 = (n0 < N_NODES) ? __ldg(&ns[n0]) : 0.f;
        float s1 = (n1 < N_NODES) ? __ldg(&ns[n1]) : 0.f;
#pragma unroll
        for (int t = 0; t < 16; t++) {
            int j0 = t * 8 + tig * 2;
            float bb0 = __ldg(&b2[j0]), bb1 = __ldg(&b2[j0 + 1]);
            float r0 = fmaxf(c[t][0] + bb0, 0.f) * s0;
            float r1 = fmaxf(c[t][1] + bb1, 0.f) * s0;
            float r2 = fmaxf(c[t][2] + bb0, 0.f) * s1;
            float r3 = fmaxf(c[t][3] + bb1, 0.f) * s1;
            __half2 h0 = __float22half2_rn(make_float2(r0, r1));
            __half2 h1 = __float22half2_rn(make_float2(r2, r3));
            *(unsigned*)(sH + ln0 * 136 + j0) = *(unsigned*)&h0;
            *(unsigned*)(sH + ln1 * 136 + j0) = *(unsigned*)&h1;
        }
    }
    __syncthreads();

    float c2[8][4];
#pragma unroll
    for (int t = 0; t < 8; t++) { c2[t][0] = c2[t][1] = c2[t][2] = c2[t][3] = 0.f; }

    {
        const __half* xw = sH + wid * 16 * 136;
#pragma unroll
        for (int k0 = 0; k0 < 128; k0 += 16) {
            const __half* ap = xw + (size_t)(lane & 15) * 136 + k0 + ((lane >> 4) << 3);
            unsigned aaddr = (unsigned)__cvta_generic_to_shared(ap);
            unsigned a0, a1, a2, a3;
            asm volatile("ldmatrix.sync.aligned.m8n8.x4.shared.b16 {%0,%1,%2,%3}, [%4];"
                         : "=r"(a0), "=r"(a1), "=r"(a2), "=r"(a3) : "r"(aaddr));
#pragma unroll
            for (int t = 0; t < 8; t++) {
                unsigned b0 = *(const unsigned*)&sW3[(k0 / 2 + tig)     * 72 + t * 8 + g];
                unsigned b1 = *(const unsigned*)&sW3[(k0 / 2 + 4 + tig) * 72 + t * 8 + g];
                asm volatile("mma.sync.aligned.m16n8k16.row.col.f32.f16.f16.f32 "
                             "{%0,%1,%2,%3}, {%4,%5,%6,%7}, {%8,%9}, {%0,%1,%2,%3};"
                             : "+f"(c2[t][0]), "+f"(c2[t][1]), "+f"(c2[t][2]), "+f"(c2[t][3])
                             : "r"(a0), "r"(a1), "r"(a2), "r"(a3), "r"(b0), "r"(b1));
            }
        }
    }

    {
        int n0 = base + wid * 16 + g;
        int n1 = n0 + 8;
#pragma unroll
        for (int t = 0; t < 8; t++) {
            int j0 = t * 8 + tig * 2;
            if (n0 < N_NODES) {
                __half2 h = __float22half2_rn(make_float2(c2[t][0], c2[t][1]));
                *(unsigned*)(out + (size_t)n0 * 64 + j0) = *(unsigned*)&h;
            }
            if (n1 < N_NODES) {
                __half2 h = __float22half2_rn(make_float2(c2[t][2], c2[t][3]));
                *(unsigned*)(out + (size_t)n1 * 64 + j0) = *(unsigned*)&h;
            }
        }
    }
}

// ---------------- CSR gather: warp/node, software-pipelined srcsrt prefetch -------
// MODE 0: out(fp16) = sum * nd                  (L2 mm input, nd folded)
// MODE 1: out(fp16) = relu(sum*nd + b) * ns     (L1 output)
// MODE 2: out(fp16) = relu(sum*nd + b)          (L3 output, pool input)
template <int MODE>
__global__ void k_gather(const __half* __restrict__ tin, const float* __restrict__ bias,
                         __half* __restrict__ outp) {
    const int lane = threadIdx.x & 31;
    const int wid  = threadIdx.x >> 5;
    const int n    = blockIdx.x * 8 + wid;
    const int grp  = lane >> 3;             // 0..3: edge slot
    const int col  = lane & 7;              // uint4 (8 halves) within 64-half row

    int beg = __ldg(&g_rowptr[n]);
    int end = beg + __ldg(&g_cnt_in[n]);    // unordered-bucket CSR

    const uint4* t16 = (const uint4*)tin;
    float a0 = 0.f, a1 = 0.f, a2 = 0.f, a3 = 0.f;
    float a4 = 0.f, a5 = 0.f, a6 = 0.f, a7 = 0.f;

    // prefetch first srcsrt chunk (pad region holds dummy ids past N_EDGES)
    int sv = N_NODES;
    if (lane < 8) {
        int ee = beg + lane;
        sv = (ee < end) ? __ldg(&g_srcsrt[ee]) : N_NODES;
    }

    for (int e = beg; e < end; e += 8) {
        int sv_cur = sv;
        // prefetch next chunk before consuming current rows
        int e2 = e + 8;
        if (lane < 8) {
            int ee = e2 + lane;
            sv = (ee < end) ? __ldg(&g_srcsrt[ee]) : N_NODES;
        }
        int s0 = __shfl_sync(0xFFFFFFFFu, sv_cur, grp);      // edges e+0..e+3
        int s1 = __shfl_sync(0xFFFFFFFFu, sv_cur, 4 + grp);  // edges e+4..e+7
        uint4 v0 = __ldg(&t16[(size_t)s0 * 8 + col]);
        uint4 v1 = __ldg(&t16[(size_t)s1 * 8 + col]);
        float2 f;
        f = __half22float2(*(__half2*)&v0.x); a0 += f.x; a1 += f.y;
        f = __half22float2(*(__half2*)&v0.y); a2 += f.x; a3 += f.y;
        f = __half22float2(*(__half2*)&v0.z); a4 += f.x; a5 += f.y;
        f = __half22float2(*(__half2*)&v0.w); a6 += f.x; a7 += f.y;
        f = __half22float2(*(__half2*)&v1.x); a0 += f.x; a1 += f.y;
        f = __half22float2(*(__half2*)&v1.y); a2 += f.x; a3 += f.y;
        f = __half22float2(*(__half2*)&v1.z); a4 += f.x; a5 += f.y;
        f = __half22float2(*(__half2*)&v1.w); a6 += f.x; a7 += f.y;
    }

    // reduce across the 4 edge-groups (lanes sharing the same col)
#pragma unroll
    for (int off = 8; off <= 16; off <<= 1) {
        a0 += __shfl_xor_sync(0xFFFFFFFFu, a0, off);
        a1 += __shfl_xor_sync(0xFFFFFFFFu, a1, off);
        a2 += __shfl_xor_sync(0xFFFFFFFFu, a2, off);
        a3 += __shfl_xor_sync(0xFFFFFFFFu, a3, off);
        a4 += __shfl_xor_sync(0xFFFFFFFFu, a4, off);
        a5 += __shfl_xor_sync(0xFFFFFFFFu, a5, off);
        a6 += __shfl_xor_sync(0xFFFFFFFFu, a6, off);
        a7 += __shfl_xor_sync(0xFFFFFFFFu, a7, off);
    }

    if (lane < 8) {
        float nd = __ldg(&g_nd[n]);
        float r0, r1, r2, r3, r4, r5, r6, r7;
        if (MODE == 0) {
            r0 = a0 * nd; r1 = a1 * nd; r2 = a2 * nd; r3 = a3 * nd;
            r4 = a4 * nd; r5 = a5 * nd; r6 = a6 * nd; r7 = a7 * nd;
        } else {
            const float4* b4 = (const float4*)bias;
            float4 ba = b4[col * 2], bb = b4[col * 2 + 1];
            r0 = fmaxf(a0 * nd + ba.x, 0.f);
            r1 = fmaxf(a1 * nd + ba.y, 0.f);
            r2 = fmaxf(a2 * nd + ba.z, 0.f);
            r3 = fmaxf(a3 * nd + ba.w, 0.f);
            r4 = fmaxf(a4 * nd + bb.x, 0.f);
            r5 = fmaxf(a5 * nd + bb.y, 0.f);
            r6 = fmaxf(a6 * nd + bb.z, 0.f);
            r7 = fmaxf(a7 * nd + bb.w, 0.f);
            if (MODE == 1) {
                float ns = __ldg(&g_ns[n]);
                r0 *= ns; r1 *= ns; r2 *= ns; r3 *= ns;
                r4 *= ns; r5 *= ns; r6 *= ns; r7 *= ns;
            }
        }
        __half2 h0 = __float22half2_rn(make_float2(r0, r1));
        __half2 h1 = __float22half2_rn(make_float2(r2, r3));
        __half2 h2 = __float22half2_rn(make_float2(r4, r5));
        __half2 h3 = __float22half2_rn(make_float2(r6, r7));
        uint4 u;
        u.x = *(unsigned*)&h0; u.y = *(unsigned*)&h1;
        u.z = *(unsigned*)&h2; u.w = *(unsigned*)&h3;
        ((uint4*)outp)[(size_t)n * 8 + col] = u;
    }
}

// ---------------- graph pooling (graph_ids sorted, fp16 input) --------------------
__global__ void k_pool(const __half* __restrict__ h, const int* __restrict__ gid) {
    int f = threadIdx.x & 63;
    int r = threadIdx.x >> 6;
    int start = blockIdx.x * 512;
    int end = min(start + 512, N_NODES);
    float acc = 0.f;
    int cur = -1;
    for (int n = start + r; n < end; n += 4) {
        int g = gid[n];
        if (g != cur) {
            if (cur >= 0) atomicAdd(&g_hg[cur * 64 + f], acc);
            cur = g; acc = 0.f;
        }
        acc += __half2float(h[(size_t)n * 64 + f]);
    }
    if (cur >= 0) atomicAdd(&g_hg[cur * 64 + f], acc);
}

// ---------------- head: out = tanh(hg) @ Wd + bd ---------------------------------
__global__ void k_final(const float* __restrict__ Wd, const float* __restrict__ bd,
                        float* __restrict__ out) {
    int t = threadIdx.x;
    if (t >= N_GRAPHS * 10) return;
    int g = t / 10, c = t % 10;
    float acc = bd[c];
#pragma unroll 8
    for (int k = 0; k < 64; k++)
        acc += tanhf(g_hg[g * 64 + k]) * Wd[k * 10 + c];
    out[t] = acc;
}

// ---------------- host orchestration ----------------------------------------------
extern "C" void kernel_launch(void* const* d_in, const int* in_sizes, int n_in,
                              void* d_out, int out_size) {
    const float* in_feat = (const float*)d_in[0];
    const int*   src     = (const int*)  d_in[1];
    const int*   dst     = (const int*)  d_in[2];
    const int*   gid     = (const int*)  d_in[3];
    const float* W1 = (const float*)d_in[4];
    const float* b1 = (const float*)d_in[5];
    const float* W2 = (const float*)d_in[6];
    const float* b2 = (const float*)d_in[7];
    const float* W3 = (const float*)d_in[8];
    const float* b3 = (const float*)d_in[9];
    const float* Wd = (const float*)d_in[10];
    const float* bd = (const float*)d_in[11];
    float* out = (float*)d_out;

    float *p_ns;
    __half *p_th, *p_mh, *p_hh;
    __half2 *p_w1, *p_w2, *p_w3;
    cudaGetSymbolAddress((void**)&p_ns, g_ns);
    cudaGetSymbolAddress((void**)&p_th, g_th);
    cudaGetSymbolAddress((void**)&p_mh, g_mh);
    cudaGetSymbolAddress((void**)&p_hh, g_hh);
    cudaGetSymbolAddress((void**)&p_w1, g_w1);
    cudaGetSymbolAddress((void**)&p_w2, g_w2);
    cudaGetSymbolAddress((void**)&p_w3, g_w3);

    const int TPB = 256;
    const int E4_BLKS   = (N_EDGES / 4 + TPB - 1) / TPB;  // 3125
    const int GATH_BLKS = N_NODES / 8;                    // 12500 (exact)
    const int MM_BLKS   = (N_NODES + 127) / 128;          // 782

    const int SM1  = 128 * 136 * 2 + 64 * 72 * 4;         // 53248
    const int SM23 = 89088;
    cudaFuncSetAttribute(k_mmtc<128, 64, false, false, false, true>,
                         cudaFuncAttributeMaxDynamicSharedMemorySize, SM1);
    cudaFuncSetAttribute(k_mm23,
                         cudaFuncAttributeMaxDynamicSharedMemorySize, SM23);

    // ---- single stream; gather1 is the 6th launch (ncu -s 5 -c 1 profiles it) ----
    k_zero <<<NBLK, TPB>>>(W1, W2, W3);                           // 1
    k_hist <<<E4_BLKS, TPB>>>(src, dst);                          // 2
    k_scanA<<<NBLK, TPB>>>();                                     // 3
    k_fill <<<E4_BLKS, TPB>>>(src, dst);                          // 4
    k_mmtc<128, 64, false, false, false, true><<<MM_BLKS, TPB, SM1>>>(
        in_feat, p_w1, nullptr, nullptr, p_ns, p_th);             // 5
    k_gather<1><<<GATH_BLKS, TPB>>>(p_th, b1, p_mh);              // 6  <- profiled
    k_gather<0><<<GATH_BLKS, TPB>>>(p_mh, nullptr, p_th);         // 7
    k_mm23<<<MM_BLKS, TPB, SM23>>>(p_th, p_w2, b2, p_ns, p_w3, p_hh); // 8
    k_gather<2><<<GATH_BLKS, TPB>>>(p_hh, b3, p_mh);              // 9
    k_pool <<<(N_NODES + 511) / 512, TPB>>>(p_mh, gid);           // 10
    k_final<<<1, N_GRAPHS * 10>>>(Wd, bd, out);                   // 11
}